// round 6
// baseline (speedup 1.0000x reference)
#include <cuda_runtime.h>
#include <cuda_bf16.h>
#include <cstdint>
#include <math.h>

#define BATCH   16384
#define FK      64
#define VISD    2048
#define HID     512
#define NUSERS  1000000
#define VOCAB   (NUSERS + 24 + 2 + 8 + 40)

// Scratch (allocation-free rule: __device__ globals)
__device__ __nv_bfloat16 g_xh [BATCH * 384];   // DNN input, bf16
__device__ __nv_bfloat16 g_h1h[BATCH * HID];   // hidden1, bf16
__device__ __nv_bfloat16 g_h2h[BATCH * HID];   // hidden2, bf16
__device__ __nv_bfloat16 g_w1h[HID * 384];     // w1 converted
__device__ __nv_bfloat16 g_w2h[HID * HID];     // w2 converted
__device__ float         g_fm [BATCH * 2];

// ---------------------------------------------------------------------------
// helpers (portable PTX only — harness targets compute_103, no 'a' features)
// ---------------------------------------------------------------------------
__device__ __forceinline__ uint32_t smem_u32(const void* p) {
    uint32_t a;
    asm("{ .reg .u64 t; cvta.to.shared.u64 t, %1; cvt.u32.u64 %0, t; }"
        : "=r"(a) : "l"(p));
    return a;
}
__device__ __forceinline__ void cp16(uint32_t s, const void* g) {
    asm volatile("cp.async.cg.shared.global [%0], [%1], 16;" :: "r"(s), "l"(g));
}
__device__ __forceinline__ void cp_commit() {
    asm volatile("cp.async.commit_group;" ::: "memory");
}
template<int N> __device__ __forceinline__ void cp_wait() {
    asm volatile("cp.async.wait_group %0;" :: "n"(N) : "memory");
}
// Raw fp32 bits fed to tf32 MMA == RZ-truncated tf32.
__device__ __forceinline__ void mma_tf32(float d[4], const uint32_t a[4],
                                         const uint32_t b[2]) {
    asm volatile(
        "mma.sync.aligned.m16n8k8.row.col.f32.tf32.tf32.f32 "
        "{%0,%1,%2,%3}, {%4,%5,%6,%7}, {%8,%9}, {%0,%1,%2,%3};"
        : "+f"(d[0]), "+f"(d[1]), "+f"(d[2]), "+f"(d[3])
        : "r"(a[0]), "r"(a[1]), "r"(a[2]), "r"(a[3]), "r"(b[0]), "r"(b[1]));
}
__device__ __forceinline__ void mma_bf16(float d[4], const uint32_t a[4],
                                         const uint32_t b[2]) {
    asm volatile(
        "mma.sync.aligned.m16n8k16.row.col.f32.bf16.bf16.f32 "
        "{%0,%1,%2,%3}, {%4,%5,%6,%7}, {%8,%9}, {%0,%1,%2,%3};"
        : "+f"(d[0]), "+f"(d[1]), "+f"(d[2]), "+f"(d[3])
        : "r"(a[0]), "r"(a[1]), "r"(a[2]), "r"(a[3]), "r"(b[0]), "r"(b[1]));
}
__device__ __forceinline__ uint32_t pack_bf16(float lo, float hi) {
    uint32_t r;
    asm("cvt.rn.bf16x2.f32 %0, %1, %2;" : "=r"(r) : "f"(hi), "f"(lo));
    return r;
}

// ---------------------------------------------------------------------------
// FRONT kernel: block-range fused  [vis tf32 GEMM | embed+FM | weight conv]
//   blocks [0, 256)        : vis = visual @ visu_w^T + visu_b -> bf16 x[:,320:384]
//   blocks [256, 4352)     : embeddings, FM 1st+2nd order -> x[:,0:320], g_fm
//   blocks [4352, 4800)    : w1,w2 fp32 -> bf16
// ---------------------------------------------------------------------------
#define VIS_BLKS   256
#define EMB_BLKS   4096
#define CONV_BLKS  448

__global__ __launch_bounds__(256, 2) void front_kernel(
    const int* __restrict__ uid, const int* __restrict__ hour,
    const float* __restrict__ visual, const float* __restrict__ scale,
    const int* __restrict__ gender, const int* __restrict__ age,
    const int* __restrict__ attr,
    const float* __restrict__ user_emb, const float* __restrict__ hour_emb,
    const float* __restrict__ gender_emb, const float* __restrict__ age_emb,
    const float* __restrict__ attr_emb,
    const float* __restrict__ visu_w, const float* __restrict__ visu_b,
    const float* __restrict__ fm_w, const float* __restrict__ fm_b,
    const float* __restrict__ w1, const float* __restrict__ w2)
{
    const int blk = blockIdx.x;
    const int tid = threadIdx.x;

    if (blk < VIS_BLKS) {
        // ================= vis GEMM: 64x64 tile, K=2048, 3-stage pipeline ==
        constexpr int BM = 64, BN = 64, BK = 32, S = 3;
        constexpr int LDT = 36;
        constexpr int WM = 2, WN = 4, TN = 2;     // 8 warps: 2x4, warp 32x16
        constexpr int ASZ = BM * LDT;
        constexpr int WSZ = BN * LDT;

        extern __shared__ float sm[];
        float* sA = sm;                            // [S][ASZ]
        float* sW = sm + S * ASZ;                  // [S][WSZ]
        __shared__ float sbias[BN];

        const int m0 = blk * BM;
        const int NC = VISD / BK;                  // 64

        if (tid < BN) sbias[tid] = visu_b[tid];

        const uint32_t sAu = smem_u32(sA);
        const uint32_t sWu = smem_u32(sW);

        auto load_tiles = [&](int c) {
            const int st = c % S;
            const int k0 = c * BK;
            #pragma unroll
            for (int j = 0; j < BM / 32; j++) {
                int i = tid + j * 256;
                int r = i >> 3, sg = i & 7;
                cp16(sAu + (st * ASZ + r * LDT) * 4 + sg * 16,
                     visual + (size_t)(m0 + r) * VISD + k0 + sg * 4);
            }
            #pragma unroll
            for (int j = 0; j < BN / 32; j++) {
                int i = tid + j * 256;
                int r = i >> 3, sg = i & 7;
                cp16(sWu + (st * WSZ + r * LDT) * 4 + sg * 16,
                     visu_w + (size_t)r * VISD + k0 + sg * 4);
            }
        };

        const int lane = tid & 31, warp = tid >> 5;
        const int g = lane >> 2, t = lane & 3;
        const int wm = warp % WM, wn = warp / WM;
        const int mbase = wm * 32;
        const int nbase = wn * (BN / WN);

        float acc[2][TN][4] = {};

        load_tiles(0); cp_commit();
        load_tiles(1); cp_commit();

        for (int c = 0; c < NC; c++) {
            cp_wait<1>();
            __syncthreads();
            if (c + 2 < NC) load_tiles(c + 2);
            cp_commit();

            const uint32_t* pa = (const uint32_t*)(sA + (c % S) * ASZ);
            const uint32_t* pw = (const uint32_t*)(sW + (c % S) * WSZ);

            #pragma unroll
            for (int ks = 0; ks < 4; ks++) {
                const int col = ks * 8 + t;
                uint32_t af[2][4], bf[TN][2];
                #pragma unroll
                for (int tm = 0; tm < 2; tm++) {
                    const int row = mbase + tm * 16 + g;
                    af[tm][0] = pa[ row      * LDT + col    ];
                    af[tm][1] = pa[(row + 8) * LDT + col    ];
                    af[tm][2] = pa[ row      * LDT + col + 4];
                    af[tm][3] = pa[(row + 8) * LDT + col + 4];
                }
                #pragma unroll
                for (int tn = 0; tn < TN; tn++) {
                    const int r = nbase + tn * 8 + g;
                    bf[tn][0] = pw[r * LDT + col    ];
                    bf[tn][1] = pw[r * LDT + col + 4];
                }
                #pragma unroll
                for (int tm = 0; tm < 2; tm++)
                    #pragma unroll
                    for (int tn = 0; tn < TN; tn++)
                        mma_tf32(acc[tm][tn], af[tm], bf[tn]);
            }
        }

        #pragma unroll
        for (int tm = 0; tm < 2; tm++) {
            #pragma unroll
            for (int tn = 0; tn < TN; tn++) {
                const int ncol = nbase + tn * 8 + 2 * t;
                const float b0 = sbias[ncol], b1 = sbias[ncol + 1];
                #pragma unroll
                for (int half = 0; half < 2; half++) {
                    const int row = m0 + mbase + tm * 16 + g + half * 8;
                    float vx = acc[tm][tn][half * 2 + 0] + b0;
                    float vy = acc[tm][tn][half * 2 + 1] + b1;
                    *(uint32_t*)(g_xh + (size_t)row * 384 + 320 + ncol) =
                        pack_bf16(vx, vy);
                }
            }
        }
    } else if (blk < VIS_BLKS + EMB_BLKS) {
        // ================= embeddings + FM ==================================
        const int eb = blk - VIS_BLKS;
        int s = tid >> 6;
        int k = tid & 63;
        int b = eb * 4 + s;

        int u  = uid[b];
        int h  = hour[b];
        int g  = gender[b];
        int a  = age[b];
        int at = attr[b];
        float sc = scale[b];

        float e0 = user_emb[(size_t)u * 64 + k];
        float e1 = hour_emb[h * 64 + k];
        float e2 = sc * tanhf(gender_emb[g * 64 + k]);
        float e3 = sc * tanhf(attr_emb[at * 64 + k]);
        float e4 = sc * tanhf(age_emb[a * 64 + k]);

        __nv_bfloat16* xb = g_xh + (size_t)b * 384;
        xb[      k] = __float2bfloat16_rn(e0);
        xb[ 64 + k] = __float2bfloat16_rn(e1);
        xb[128 + k] = __float2bfloat16_rn(e2);
        xb[192 + k] = __float2bfloat16_rn(e3);
        xb[256 + k] = __float2bfloat16_rn(e4);

        float su = e0 + e1 + e2 + e3 + e4;
        float sq = e0*e0 + e1*e1 + e2*e2 + e3*e3 + e4*e4;
        float so = su * su - sq;

        #pragma unroll
        for (int o = 16; o > 0; o >>= 1)
            so += __shfl_down_sync(0xffffffffu, so, o);

        __shared__ float red[4][2];
        if ((k & 31) == 0) red[s][k >> 5] = so;
        __syncthreads();

        if (k == 0) {
            float second = 0.5f * (red[s][0] + red[s][1]);
            long c0 = u;
            long c1 = NUSERS + h;
            long c2 = NUSERS + 24 + g;
            long c3 = NUSERS + 26 + a;
            long c4 = NUSERS + 34 + at;
            #pragma unroll
            for (int j = 0; j < 2; j++) {
                const float* w = fm_w + (size_t)j * VOCAB;
                g_fm[b * 2 + j] =
                    w[c0] + w[c1] + w[c2] + w[c3] + w[c4] + fm_b[j] + second;
            }
        }
    } else {
        // ================= weight conversion ================================
        const int N1 = HID * 384 / 4;
        int i = (blk - VIS_BLKS - EMB_BLKS) * 256 + tid;
        if (i < N1) {
            float4 v = ((const float4*)w1)[i];
            uint2 o = { pack_bf16(v.x, v.y), pack_bf16(v.z, v.w) };
            ((uint2*)g_w1h)[i] = o;
        } else {
            int j = i - N1;
            float4 v = ((const float4*)w2)[j];
            uint2 o = { pack_bf16(v.x, v.y), pack_bf16(v.z, v.w) };
            ((uint2*)g_w2h)[j] = o;
        }
    }
}

// ---------------------------------------------------------------------------
// bf16 tensor-core GEMM (MLP layers): C = A[M,K] @ W[N,K]^T + bias, relu
// m16n8k16; BK=32 elements; 3-stage cp.async, single sync per iteration.
// ---------------------------------------------------------------------------
template<int BM, int BN>
__global__ __launch_bounds__(256, 2) void gemm_bf16k(
    const __nv_bfloat16* __restrict__ A, int lda,
    const __nv_bfloat16* __restrict__ W,
    const float* __restrict__ bias,
    __nv_bfloat16* __restrict__ C, int ldc,
    int K, int relu)
{
    constexpr int BK  = 32;
    constexpr int S   = 3;
    constexpr int LDW = 20;                 // u32 words per smem row (16+4 pad)
    constexpr int WM  = BM / 32;
    constexpr int WN  = 8 / WM;
    constexpr int TN  = BN / WN / 8;
    constexpr int ASZ = BM * LDW;
    constexpr int WSZ = BN * LDW;

    extern __shared__ uint32_t smw[];
    uint32_t* sA = smw;                     // [S][ASZ]
    uint32_t* sW = smw + S * ASZ;           // [S][WSZ]
    __shared__ float sbias[BN];

    const int tid = threadIdx.x;
    const int m0  = blockIdx.y * BM;
    const int n0  = blockIdx.x * BN;
    const int NC  = K / BK;

    if (tid < BN) sbias[tid] = bias[n0 + tid];

    const uint32_t sAu = smem_u32(sA);
    const uint32_t sWu = smem_u32(sW);

    auto load_tiles = [&](int c) {
        const int st = c % S;
        const int k0 = c * BK;
        #pragma unroll
        for (int j = 0; j < BM / 64; j++) {
            int i = tid + j * 256;
            int r = i >> 2, sg = i & 3;
            cp16(sAu + (st * ASZ + r * LDW + sg * 4) * 4,
                 A + (size_t)(m0 + r) * lda + k0 + sg * 8);
        }
        #pragma unroll
        for (int j = 0; j < BN / 64; j++) {
            int i = tid + j * 256;
            int r = i >> 2, sg = i & 3;
            cp16(sWu + (st * WSZ + r * LDW + sg * 4) * 4,
                 W + (size_t)(n0 + r) * K + k0 + sg * 8);
        }
    };

    const int lane = tid & 31, warp = tid >> 5;
    const int g = lane >> 2, t = lane & 3;
    const int wm = warp % WM, wn = warp / WM;
    const int mbase = wm * 32;
    const int nbase = wn * (BN / WN);

    float acc[2][TN][4] = {};

    load_tiles(0); cp_commit();
    load_tiles(1); cp_commit();

    for (int c = 0; c < NC; c++) {
        cp_wait<1>();
        __syncthreads();
        if (c + 2 < NC) load_tiles(c + 2);
        cp_commit();

        const uint32_t* pa = sA + (c % S) * ASZ;
        const uint32_t* pw = sW + (c % S) * WSZ;

        #pragma unroll
        for (int ks = 0; ks < 2; ks++) {
            const int col = ks * 8 + t;
            uint32_t af[2][4], bf[TN][2];
            #pragma unroll
            for (int tm = 0; tm < 2; tm++) {
                const int row = mbase + tm * 16 + g;
                af[tm][0] = pa[ row      * LDW + col    ];
                af[tm][1] = pa[(row + 8) * LDW + col    ];
                af[tm][2] = pa[ row      * LDW + col + 4];
                af[tm][3] = pa[(row + 8) * LDW + col + 4];
            }
            #pragma unroll
            for (int tn = 0; tn < TN; tn++) {
                const int r = nbase + tn * 8 + g;
                bf[tn][0] = pw[r * LDW + col    ];
                bf[tn][1] = pw[r * LDW + col + 4];
            }
            #pragma unroll
            for (int tm = 0; tm < 2; tm++)
                #pragma unroll
                for (int tn = 0; tn < TN; tn++)
                    mma_bf16(acc[tm][tn], af[tm], bf[tn]);
        }
    }

    #pragma unroll
    for (int tm = 0; tm < 2; tm++) {
        #pragma unroll
        for (int tn = 0; tn < TN; tn++) {
            const int ncol = nbase + tn * 8 + 2 * t;
            const float b0 = sbias[ncol], b1 = sbias[ncol + 1];
            const int gcol = n0 + ncol;
            #pragma unroll
            for (int half = 0; half < 2; half++) {
                const int row = m0 + mbase + tm * 16 + g + half * 8;
                float vx = acc[tm][tn][half * 2 + 0] + b0;
                float vy = acc[tm][tn][half * 2 + 1] + b1;
                if (relu) { vx = fmaxf(vx, 0.f); vy = fmaxf(vy, 0.f); }
                *(uint32_t*)(C + (size_t)row * ldc + gcol) = pack_bf16(vx, vy);
            }
        }
    }
}

// ---------------------------------------------------------------------------
// Final: logits = fm + h2 @ w3^T + b3 ; softmax over 2 classes.
// ---------------------------------------------------------------------------
__global__ void final_kernel(const float* __restrict__ w3,
                             const float* __restrict__ b3,
                             float* __restrict__ out)
{
    __shared__ float w3s[2 * HID];
    int t = threadIdx.x;
    for (int i = t; i < 2 * HID; i += 256) w3s[i] = w3[i];
    __syncthreads();

    int warp = t >> 5, lane = t & 31;
    int b = blockIdx.x * 8 + warp;
    const __nv_bfloat16* h = g_h2h + (size_t)b * HID;

    float d0 = 0.f, d1 = 0.f;
    #pragma unroll
    for (int i = lane; i < HID; i += 32) {
        float hv = __bfloat162float(h[i]);
        d0 = fmaf(hv, w3s[i],       d0);
        d1 = fmaf(hv, w3s[HID + i], d1);
    }
    #pragma unroll
    for (int o = 16; o > 0; o >>= 1) {
        d0 += __shfl_down_sync(0xffffffffu, d0, o);
        d1 += __shfl_down_sync(0xffffffffu, d1, o);
    }
    if (lane == 0) {
        float l0 = g_fm[b * 2 + 0] + b3[0] + d0;
        float l1 = g_fm[b * 2 + 1] + b3[1] + d1;
        float m  = fmaxf(l0, l1);
        float e0 = expf(l0 - m), e1 = expf(l1 - m);
        float inv = 1.0f / (e0 + e1);
        out[b * 2 + 0] = e0 * inv;
        out[b * 2 + 1] = e1 * inv;
    }
}

// ---------------------------------------------------------------------------
extern "C" void kernel_launch(void* const* d_in, const int* in_sizes, int n_in,
                              void* d_out, int out_size)
{
    const int*   uid        = (const int*)  d_in[0];
    const int*   hour       = (const int*)  d_in[1];
    const float* visual     = (const float*)d_in[2];
    const float* scale      = (const float*)d_in[3];
    const int*   gender     = (const int*)  d_in[4];
    const int*   age        = (const int*)  d_in[5];
    const int*   attribute  = (const int*)  d_in[6];
    const float* user_emb   = (const float*)d_in[7];
    const float* hour_emb   = (const float*)d_in[8];
    const float* gender_emb = (const float*)d_in[9];
    const float* age_emb    = (const float*)d_in[10];
    const float* attr_emb   = (const float*)d_in[11];
    const float* visu_w     = (const float*)d_in[12];
    const float* visu_b     = (const float*)d_in[13];
    const float* fm_w       = (const float*)d_in[14];
    const float* fm_b       = (const float*)d_in[15];
    const float* w1         = (const float*)d_in[16];
    const float* b1         = (const float*)d_in[17];
    const float* w2         = (const float*)d_in[18];
    const float* b2         = (const float*)d_in[19];
    const float* w3         = (const float*)d_in[20];
    const float* b3         = (const float*)d_in[21];
    float* out = (float*)d_out;

    __nv_bfloat16 *xhp, *h1p, *h2p, *w1p, *w2p;
    cudaGetSymbolAddress((void**)&xhp, g_xh);
    cudaGetSymbolAddress((void**)&h1p, g_h1h);
    cudaGetSymbolAddress((void**)&h2p, g_h2h);
    cudaGetSymbolAddress((void**)&w1p, g_w1h);
    cudaGetSymbolAddress((void**)&w2p, g_w2h);

    const int SM_FRONT = 3 * (64 + 64) * 36 * 4;       // 55,296 B
    const int SM_MLP   = 3 * (128 + 128) * 20 * 4;     // 61,440 B
    cudaFuncSetAttribute(front_kernel, cudaFuncAttributeMaxDynamicSharedMemorySize, SM_FRONT);
    cudaFuncSetAttribute(gemm_bf16k<128, 128>, cudaFuncAttributeMaxDynamicSharedMemorySize, SM_MLP);

    // 1) fused front: vis GEMM + embeddings/FM + weight conversion
    front_kernel<<<VIS_BLKS + EMB_BLKS + CONV_BLKS, 256, SM_FRONT>>>(
        uid, hour, visual, scale, gender, age, attribute,
        user_emb, hour_emb, gender_emb, age_emb, attr_emb,
        visu_w, visu_b, fm_w, fm_b, w1, w2);

    // 2) h1 = relu(x @ w1^T + b1)   bf16 (512 CTAs)
    gemm_bf16k<128, 128><<<dim3(HID / 128, BATCH / 128), 256, SM_MLP>>>(
        xhp, 384, w1p, b1, h1p, HID, 384, 1);

    // 3) h2 = relu(h1 @ w2^T + b2)  bf16 (512 CTAs)
    gemm_bf16k<128, 128><<<dim3(HID / 128, BATCH / 128), 256, SM_MLP>>>(
        h1p, HID, w2p, b2, h2p, HID, HID, 1);

    // 4) logits + softmax
    final_kernel<<<BATCH / 8, 256>>>(w3, b3, out);
}

// round 7
// speedup vs baseline: 1.1669x; 1.1669x over previous
#include <cuda_runtime.h>
#include <cuda_bf16.h>
#include <cstdint>
#include <math.h>

#define BATCH   16384
#define FK      64
#define VISD    2048
#define HID     512
#define NUSERS  1000000
#define VOCAB   (NUSERS + 24 + 2 + 8 + 40)

// Scratch (allocation-free rule: __device__ globals)
__device__ __nv_bfloat16 g_xh [BATCH * 384];   // DNN input, bf16
__device__ __nv_bfloat16 g_h1h[BATCH * HID];   // hidden1, bf16
__device__ __nv_bfloat16 g_w1h[HID * 384];     // w1 converted
__device__ __nv_bfloat16 g_w2h[HID * HID];     // w2 converted
__device__ float         g_fm [BATCH * 2];
__device__ float2        g_part[BATCH * 8];    // per-(row, nblock*2+wn) logit partials

// ---------------------------------------------------------------------------
// helpers (portable PTX only — harness targets compute_103, no 'a' features)
// ---------------------------------------------------------------------------
__device__ __forceinline__ uint32_t smem_u32(const void* p) {
    uint32_t a;
    asm("{ .reg .u64 t; cvta.to.shared.u64 t, %1; cvt.u32.u64 %0, t; }"
        : "=r"(a) : "l"(p));
    return a;
}
__device__ __forceinline__ void cp16(uint32_t s, const void* g) {
    asm volatile("cp.async.cg.shared.global [%0], [%1], 16;" :: "r"(s), "l"(g));
}
__device__ __forceinline__ void cp_commit() {
    asm volatile("cp.async.commit_group;" ::: "memory");
}
template<int N> __device__ __forceinline__ void cp_wait() {
    asm volatile("cp.async.wait_group %0;" :: "n"(N) : "memory");
}
// Raw fp32 bits fed to tf32 MMA == RZ-truncated tf32.
__device__ __forceinline__ void mma_tf32(float d[4], const uint32_t a[4],
                                         const uint32_t b[2]) {
    asm volatile(
        "mma.sync.aligned.m16n8k8.row.col.f32.tf32.tf32.f32 "
        "{%0,%1,%2,%3}, {%4,%5,%6,%7}, {%8,%9}, {%0,%1,%2,%3};"
        : "+f"(d[0]), "+f"(d[1]), "+f"(d[2]), "+f"(d[3])
        : "r"(a[0]), "r"(a[1]), "r"(a[2]), "r"(a[3]), "r"(b[0]), "r"(b[1]));
}
__device__ __forceinline__ void mma_bf16(float d[4], const uint32_t a[4],
                                         const uint32_t b[2]) {
    asm volatile(
        "mma.sync.aligned.m16n8k16.row.col.f32.bf16.bf16.f32 "
        "{%0,%1,%2,%3}, {%4,%5,%6,%7}, {%8,%9}, {%0,%1,%2,%3};"
        : "+f"(d[0]), "+f"(d[1]), "+f"(d[2]), "+f"(d[3])
        : "r"(a[0]), "r"(a[1]), "r"(a[2]), "r"(a[3]), "r"(b[0]), "r"(b[1]));
}
__device__ __forceinline__ uint32_t pack_bf16(float lo, float hi) {
    uint32_t r;
    asm("cvt.rn.bf16x2.f32 %0, %1, %2;" : "=r"(r) : "f"(hi), "f"(lo));
    return r;
}

// ---------------------------------------------------------------------------
// Weight conversion: w1, w2 fp32 -> bf16
// ---------------------------------------------------------------------------
__global__ void conv_w_kernel(const float* __restrict__ w1,
                              const float* __restrict__ w2)
{
    const int N1 = HID * 384 / 4;
    int i = blockIdx.x * blockDim.x + threadIdx.x;
    if (i < N1) {
        float4 v = ((const float4*)w1)[i];
        uint2 o = { pack_bf16(v.x, v.y), pack_bf16(v.z, v.w) };
        ((uint2*)g_w1h)[i] = o;
    } else {
        int j = i - N1;
        float4 v = ((const float4*)w2)[j];
        uint2 o = { pack_bf16(v.x, v.y), pack_bf16(v.z, v.w) };
        ((uint2*)g_w2h)[j] = o;
    }
}

// ---------------------------------------------------------------------------
// tf32 GEMM (vis layer): bf16 out at column offset. 2-stage (proven R5).
// ---------------------------------------------------------------------------
template<int BM, int BN>
__global__ __launch_bounds__(256, 2) void gemm_tf32(
    const float* __restrict__ A, int lda,
    const float* __restrict__ W,
    const float* __restrict__ bias,
    __nv_bfloat16* __restrict__ C, int ldc, int ccol0,
    int K)
{
    constexpr int BK  = 32;
    constexpr int LDT = 36;
    constexpr int WM  = BM / 32;
    constexpr int WN  = 8 / WM;
    constexpr int TN  = BN / WN / 8;
    constexpr int ASZ = BM * LDT;
    constexpr int WSZ = BN * LDT;

    extern __shared__ float sm[];
    float* sA = sm;
    float* sW = sm + 2 * ASZ;
    __shared__ float sbias[BN];

    const int tid = threadIdx.x;
    const int m0  = blockIdx.y * BM;
    const int n0  = blockIdx.x * BN;
    const int NC  = K / BK;

    if (tid < BN) sbias[tid] = bias[n0 + tid];

    const uint32_t sAu = smem_u32(sA);
    const uint32_t sWu = smem_u32(sW);

    auto load_tiles = [&](int c) {
        const int st = c & 1;
        const int k0 = c * BK;
        #pragma unroll
        for (int j = 0; j < BM / 32; j++) {
            int i = tid + j * 256;
            int r = i >> 3, sg = i & 7;
            cp16(sAu + (st * ASZ + r * LDT) * 4 + sg * 16,
                 A + (size_t)(m0 + r) * lda + k0 + sg * 4);
        }
        #pragma unroll
        for (int j = 0; j < BN / 32; j++) {
            int i = tid + j * 256;
            int r = i >> 3, sg = i & 7;
            cp16(sWu + (st * WSZ + r * LDT) * 4 + sg * 16,
                 W + (size_t)(n0 + r) * K + k0 + sg * 4);
        }
    };

    const int lane = tid & 31, warp = tid >> 5;
    const int g = lane >> 2, t = lane & 3;
    const int wm = warp % WM, wn = warp / WM;
    const int mbase = wm * 32;
    const int nbase = wn * (BN / WN);

    float acc[2][TN][4] = {};

    load_tiles(0);
    cp_commit();

    for (int c = 0; c < NC; c++) {
        if (c + 1 < NC) load_tiles(c + 1);
        cp_commit();
        cp_wait<1>();
        __syncthreads();

        const uint32_t* pa = (const uint32_t*)(sA + (c & 1) * ASZ);
        const uint32_t* pw = (const uint32_t*)(sW + (c & 1) * WSZ);

        #pragma unroll
        for (int ks = 0; ks < 4; ks++) {
            const int col = ks * 8 + t;
            uint32_t af[2][4], bf[TN][2];
            #pragma unroll
            for (int tm = 0; tm < 2; tm++) {
                const int row = mbase + tm * 16 + g;
                af[tm][0] = pa[ row      * LDT + col    ];
                af[tm][1] = pa[(row + 8) * LDT + col    ];
                af[tm][2] = pa[ row      * LDT + col + 4];
                af[tm][3] = pa[(row + 8) * LDT + col + 4];
            }
            #pragma unroll
            for (int tn = 0; tn < TN; tn++) {
                const int r = nbase + tn * 8 + g;
                bf[tn][0] = pw[r * LDT + col    ];
                bf[tn][1] = pw[r * LDT + col + 4];
            }
            #pragma unroll
            for (int tm = 0; tm < 2; tm++)
                #pragma unroll
                for (int tn = 0; tn < TN; tn++)
                    mma_tf32(acc[tm][tn], af[tm], bf[tn]);
        }
        __syncthreads();
    }

    #pragma unroll
    for (int tm = 0; tm < 2; tm++) {
        #pragma unroll
        for (int tn = 0; tn < TN; tn++) {
            const int ncol = nbase + tn * 8 + 2 * t;
            const float b0 = sbias[ncol], b1 = sbias[ncol + 1];
            const int gcol = ccol0 + n0 + ncol;
            #pragma unroll
            for (int half = 0; half < 2; half++) {
                const int row = m0 + mbase + tm * 16 + g + half * 8;
                float vx = acc[tm][tn][half * 2 + 0] + b0;
                float vy = acc[tm][tn][half * 2 + 1] + b1;
                *(uint32_t*)(C + (size_t)row * ldc + gcol) = pack_bf16(vx, vy);
            }
        }
    }
}

// ---------------------------------------------------------------------------
// bf16 GEMM (mlp1): h1 = relu(x @ w1^T + b1). 2-stage (proven R5).
// ---------------------------------------------------------------------------
template<int BM, int BN>
__global__ __launch_bounds__(256, 2) void gemm_bf16k(
    const __nv_bfloat16* __restrict__ A, int lda,
    const __nv_bfloat16* __restrict__ W,
    const float* __restrict__ bias,
    __nv_bfloat16* __restrict__ C, int ldc,
    int K)
{
    constexpr int BK  = 32;
    constexpr int LDW = 20;
    constexpr int WM  = BM / 32;
    constexpr int WN  = 8 / WM;
    constexpr int TN  = BN / WN / 8;
    constexpr int ASZ = BM * LDW;
    constexpr int WSZ = BN * LDW;

    extern __shared__ uint32_t smw[];
    uint32_t* sA = smw;
    uint32_t* sW = smw + 2 * ASZ;
    __shared__ float sbias[BN];

    const int tid = threadIdx.x;
    const int m0  = blockIdx.y * BM;
    const int n0  = blockIdx.x * BN;
    const int NC  = K / BK;

    if (tid < BN) sbias[tid] = bias[n0 + tid];

    const uint32_t sAu = smem_u32(sA);
    const uint32_t sWu = smem_u32(sW);

    auto load_tiles = [&](int c) {
        const int st = c & 1;
        const int k0 = c * BK;
        #pragma unroll
        for (int j = 0; j < BM / 64; j++) {
            int i = tid + j * 256;
            int r = i >> 2, sg = i & 3;
            cp16(sAu + (st * ASZ + r * LDW + sg * 4) * 4,
                 A + (size_t)(m0 + r) * lda + k0 + sg * 8);
        }
        #pragma unroll
        for (int j = 0; j < BN / 64; j++) {
            int i = tid + j * 256;
            int r = i >> 2, sg = i & 3;
            cp16(sWu + (st * WSZ + r * LDW + sg * 4) * 4,
                 W + (size_t)(n0 + r) * K + k0 + sg * 8);
        }
    };

    const int lane = tid & 31, warp = tid >> 5;
    const int g = lane >> 2, t = lane & 3;
    const int wm = warp % WM, wn = warp / WM;
    const int mbase = wm * 32;
    const int nbase = wn * (BN / WN);

    float acc[2][TN][4] = {};

    load_tiles(0);
    cp_commit();

    for (int c = 0; c < NC; c++) {
        if (c + 1 < NC) load_tiles(c + 1);
        cp_commit();
        cp_wait<1>();
        __syncthreads();

        const uint32_t* pa = sA + (c & 1) * ASZ;
        const uint32_t* pw = sW + (c & 1) * WSZ;

        #pragma unroll
        for (int ks = 0; ks < 2; ks++) {
            const int col = ks * 8 + t;
            uint32_t af[2][4], bf[TN][2];
            #pragma unroll
            for (int tm = 0; tm < 2; tm++) {
                const int row = mbase + tm * 16 + g;
                af[tm][0] = pa[ row      * LDW + col    ];
                af[tm][1] = pa[(row + 8) * LDW + col    ];
                af[tm][2] = pa[ row      * LDW + col + 4];
                af[tm][3] = pa[(row + 8) * LDW + col + 4];
            }
            #pragma unroll
            for (int tn = 0; tn < TN; tn++) {
                const int r = nbase + tn * 8 + g;
                bf[tn][0] = pw[r * LDW + col    ];
                bf[tn][1] = pw[r * LDW + col + 4];
            }
            #pragma unroll
            for (int tm = 0; tm < 2; tm++)
                #pragma unroll
                for (int tn = 0; tn < TN; tn++)
                    mma_bf16(acc[tm][tn], af[tm], bf[tn]);
        }
        __syncthreads();
    }

    #pragma unroll
    for (int tm = 0; tm < 2; tm++) {
        #pragma unroll
        for (int tn = 0; tn < TN; tn++) {
            const int ncol = nbase + tn * 8 + 2 * t;
            const float b0 = sbias[ncol], b1 = sbias[ncol + 1];
            const int gcol = n0 + ncol;
            #pragma unroll
            for (int half = 0; half < 2; half++) {
                const int row = m0 + mbase + tm * 16 + g + half * 8;
                float vx = fmaxf(acc[tm][tn][half * 2 + 0] + b0, 0.f);
                float vy = fmaxf(acc[tm][tn][half * 2 + 1] + b1, 0.f);
                *(uint32_t*)(C + (size_t)row * ldc + gcol) = pack_bf16(vx, vy);
            }
        }
    }
}

// ---------------------------------------------------------------------------
// bf16 GEMM (mlp2) + fused logits: h2 = relu(h1 @ w2^T + b2) kept in regs,
// partial = h2_tile . w3_slice^T reduced across the thread quad, written to
// g_part[row][blockIdx.x*2 + wn]. h2 is never stored.
// ---------------------------------------------------------------------------
template<int BM, int BN>
__global__ __launch_bounds__(256, 2) void gemm_bf16_last(
    const __nv_bfloat16* __restrict__ A, int lda,
    const __nv_bfloat16* __restrict__ W,
    const float* __restrict__ bias,
    const float* __restrict__ w3,
    int K)
{
    constexpr int BK  = 32;
    constexpr int LDW = 20;
    constexpr int WM  = BM / 32;
    constexpr int WN  = 8 / WM;
    constexpr int TN  = BN / WN / 8;
    constexpr int ASZ = BM * LDW;
    constexpr int WSZ = BN * LDW;

    extern __shared__ uint32_t smw[];
    uint32_t* sA = smw;
    uint32_t* sW = smw + 2 * ASZ;
    __shared__ float sbias[BN];
    __shared__ float w3s[2][BN];

    const int tid = threadIdx.x;
    const int m0  = blockIdx.y * BM;
    const int n0  = blockIdx.x * BN;
    const int NC  = K / BK;

    if (tid < BN) {
        sbias[tid]  = bias[n0 + tid];
        w3s[0][tid] = w3[n0 + tid];
        w3s[1][tid] = w3[HID + n0 + tid];
    }

    const uint32_t sAu = smem_u32(sA);
    const uint32_t sWu = smem_u32(sW);

    auto load_tiles = [&](int c) {
        const int st = c & 1;
        const int k0 = c * BK;
        #pragma unroll
        for (int j = 0; j < BM / 64; j++) {
            int i = tid + j * 256;
            int r = i >> 2, sg = i & 3;
            cp16(sAu + (st * ASZ + r * LDW + sg * 4) * 4,
                 A + (size_t)(m0 + r) * lda + k0 + sg * 8);
        }
        #pragma unroll
        for (int j = 0; j < BN / 64; j++) {
            int i = tid + j * 256;
            int r = i >> 2, sg = i & 3;
            cp16(sWu + (st * WSZ + r * LDW + sg * 4) * 4,
                 W + (size_t)(n0 + r) * K + k0 + sg * 8);
        }
    };

    const int lane = tid & 31, warp = tid >> 5;
    const int g = lane >> 2, t = lane & 3;
    const int wm = warp % WM, wn = warp / WM;
    const int mbase = wm * 32;
    const int nbase = wn * (BN / WN);

    float acc[2][TN][4] = {};

    load_tiles(0);
    cp_commit();

    for (int c = 0; c < NC; c++) {
        if (c + 1 < NC) load_tiles(c + 1);
        cp_commit();
        cp_wait<1>();
        __syncthreads();

        const uint32_t* pa = sA + (c & 1) * ASZ;
        const uint32_t* pw = sW + (c & 1) * WSZ;

        #pragma unroll
        for (int ks = 0; ks < 2; ks++) {
            const int col = ks * 8 + t;
            uint32_t af[2][4], bf[TN][2];
            #pragma unroll
            for (int tm = 0; tm < 2; tm++) {
                const int row = mbase + tm * 16 + g;
                af[tm][0] = pa[ row      * LDW + col    ];
                af[tm][1] = pa[(row + 8) * LDW + col    ];
                af[tm][2] = pa[ row      * LDW + col + 4];
                af[tm][3] = pa[(row + 8) * LDW + col + 4];
            }
            #pragma unroll
            for (int tn = 0; tn < TN; tn++) {
                const int r = nbase + tn * 8 + g;
                bf[tn][0] = pw[r * LDW + col    ];
                bf[tn][1] = pw[r * LDW + col + 4];
            }
            #pragma unroll
            for (int tm = 0; tm < 2; tm++)
                #pragma unroll
                for (int tn = 0; tn < TN; tn++)
                    mma_bf16(acc[tm][tn], af[tm], bf[tn]);
        }
        __syncthreads();
    }

    // fused epilogue: relu(h2) dotted with w3 columns, quad-reduced, stored
    const int pidx = blockIdx.x * 2 + wn;          // 0..7
    #pragma unroll
    for (int tm = 0; tm < 2; tm++) {
        #pragma unroll
        for (int half = 0; half < 2; half++) {
            const int row = m0 + mbase + tm * 16 + g + half * 8;
            float s0 = 0.f, s1 = 0.f;
            #pragma unroll
            for (int tn = 0; tn < TN; tn++) {
                const int ncol = nbase + tn * 8 + 2 * t;
                float v0 = fmaxf(acc[tm][tn][half * 2 + 0] + sbias[ncol],     0.f);
                float v1 = fmaxf(acc[tm][tn][half * 2 + 1] + sbias[ncol + 1], 0.f);
                s0 = fmaf(v0, w3s[0][ncol], fmaf(v1, w3s[0][ncol + 1], s0));
                s1 = fmaf(v0, w3s[1][ncol], fmaf(v1, w3s[1][ncol + 1], s1));
            }
            s0 += __shfl_xor_sync(0xffffffffu, s0, 1);
            s0 += __shfl_xor_sync(0xffffffffu, s0, 2);
            s1 += __shfl_xor_sync(0xffffffffu, s1, 1);
            s1 += __shfl_xor_sync(0xffffffffu, s1, 2);
            if (t == 0)
                g_part[row * 8 + pidx] = make_float2(s0, s1);
        }
    }
}

// ---------------------------------------------------------------------------
// Embeddings + FM (1st + 2nd order) -> g_xh[:, 0:320], g_fm
// ---------------------------------------------------------------------------
__global__ void embed_fm_kernel(
    const int* __restrict__ uid, const int* __restrict__ hour,
    const float* __restrict__ scale,
    const int* __restrict__ gender, const int* __restrict__ age,
    const int* __restrict__ attr,
    const float* __restrict__ user_emb, const float* __restrict__ hour_emb,
    const float* __restrict__ gender_emb, const float* __restrict__ age_emb,
    const float* __restrict__ attr_emb,
    const float* __restrict__ fm_w, const float* __restrict__ fm_b)
{
    int s = threadIdx.x >> 6;
    int k = threadIdx.x & 63;
    int b = blockIdx.x * 4 + s;

    int u  = uid[b];
    int h  = hour[b];
    int g  = gender[b];
    int a  = age[b];
    int at = attr[b];
    float sc = scale[b];

    float e0 = user_emb[(size_t)u * 64 + k];
    float e1 = hour_emb[h * 64 + k];
    float e2 = sc * tanhf(gender_emb[g * 64 + k]);
    float e3 = sc * tanhf(attr_emb[at * 64 + k]);
    float e4 = sc * tanhf(age_emb[a * 64 + k]);

    __nv_bfloat16* xb = g_xh + (size_t)b * 384;
    xb[      k] = __float2bfloat16_rn(e0);
    xb[ 64 + k] = __float2bfloat16_rn(e1);
    xb[128 + k] = __float2bfloat16_rn(e2);
    xb[192 + k] = __float2bfloat16_rn(e3);
    xb[256 + k] = __float2bfloat16_rn(e4);

    float su = e0 + e1 + e2 + e3 + e4;
    float sq = e0*e0 + e1*e1 + e2*e2 + e3*e3 + e4*e4;
    float so = su * su - sq;

    #pragma unroll
    for (int o = 16; o > 0; o >>= 1)
        so += __shfl_down_sync(0xffffffffu, so, o);

    __shared__ float red[4][2];
    if ((k & 31) == 0) red[s][k >> 5] = so;
    __syncthreads();

    if (k == 0) {
        float second = 0.5f * (red[s][0] + red[s][1]);
        long c0 = u;
        long c1 = NUSERS + h;
        long c2 = NUSERS + 24 + g;
        long c3 = NUSERS + 26 + a;
        long c4 = NUSERS + 34 + at;
        #pragma unroll
        for (int j = 0; j < 2; j++) {
            const float* w = fm_w + (size_t)j * VOCAB;
            g_fm[b * 2 + j] =
                w[c0] + w[c1] + w[c2] + w[c3] + w[c4] + fm_b[j] + second;
        }
    }
}

// ---------------------------------------------------------------------------
// Softmax over (fm + b3 + sum of 8 partials), fixed summation order.
// ---------------------------------------------------------------------------
__global__ void softmax_kernel(const float* __restrict__ b3,
                               float* __restrict__ out)
{
    int b = blockIdx.x * 256 + threadIdx.x;
    float s0 = 0.f, s1 = 0.f;
    #pragma unroll
    for (int p = 0; p < 8; p++) {
        float2 v = g_part[b * 8 + p];
        s0 += v.x; s1 += v.y;
    }
    float l0 = g_fm[b * 2 + 0] + b3[0] + s0;
    float l1 = g_fm[b * 2 + 1] + b3[1] + s1;
    float m  = fmaxf(l0, l1);
    float e0 = expf(l0 - m), e1 = expf(l1 - m);
    float inv = 1.0f / (e0 + e1);
    out[b * 2 + 0] = e0 * inv;
    out[b * 2 + 1] = e1 * inv;
}

// ---------------------------------------------------------------------------
extern "C" void kernel_launch(void* const* d_in, const int* in_sizes, int n_in,
                              void* d_out, int out_size)
{
    const int*   uid        = (const int*)  d_in[0];
    const int*   hour       = (const int*)  d_in[1];
    const float* visual     = (const float*)d_in[2];
    const float* scale      = (const float*)d_in[3];
    const int*   gender     = (const int*)  d_in[4];
    const int*   age        = (const int*)  d_in[5];
    const int*   attribute  = (const int*)  d_in[6];
    const float* user_emb   = (const float*)d_in[7];
    const float* hour_emb   = (const float*)d_in[8];
    const float* gender_emb = (const float*)d_in[9];
    const float* age_emb    = (const float*)d_in[10];
    const float* attr_emb   = (const float*)d_in[11];
    const float* visu_w     = (const float*)d_in[12];
    const float* visu_b     = (const float*)d_in[13];
    const float* fm_w       = (const float*)d_in[14];
    const float* fm_b       = (const float*)d_in[15];
    const float* w1         = (const float*)d_in[16];
    const float* b1         = (const float*)d_in[17];
    const float* w2         = (const float*)d_in[18];
    const float* b2         = (const float*)d_in[19];
    const float* w3         = (const float*)d_in[20];
    const float* b3         = (const float*)d_in[21];
    float* out = (float*)d_out;

    __nv_bfloat16 *xhp, *h1p, *w1p, *w2p;
    cudaGetSymbolAddress((void**)&xhp, g_xh);
    cudaGetSymbolAddress((void**)&h1p, g_h1h);
    cudaGetSymbolAddress((void**)&w1p, g_w1h);
    cudaGetSymbolAddress((void**)&w2p, g_w2h);

    const int SM_TF = 2 * (64 + 64) * 36 * 4;            // 36,864 B
    const int SM_BF = 2 * (128 + 128) * 20 * 4;          // 40,960 B
    cudaFuncSetAttribute(gemm_tf32<64, 64>,        cudaFuncAttributeMaxDynamicSharedMemorySize, SM_TF);
    cudaFuncSetAttribute(gemm_bf16k<128, 128>,     cudaFuncAttributeMaxDynamicSharedMemorySize, SM_BF);
    cudaFuncSetAttribute(gemm_bf16_last<128, 128>, cudaFuncAttributeMaxDynamicSharedMemorySize, SM_BF);

    // fork two side branches off the capture stream
    cudaStream_t s1, s2;
    cudaStreamCreateWithFlags(&s1, cudaStreamNonBlocking);
    cudaStreamCreateWithFlags(&s2, cudaStreamNonBlocking);
    cudaEvent_t ev0, ev1, ev2;
    cudaEventCreateWithFlags(&ev0, cudaEventDisableTiming);
    cudaEventCreateWithFlags(&ev1, cudaEventDisableTiming);
    cudaEventCreateWithFlags(&ev2, cudaEventDisableTiming);

    cudaEventRecord(ev0, 0);
    cudaStreamWaitEvent(s1, ev0, 0);
    cudaStreamWaitEvent(s2, ev0, 0);

    // branch 1 (s1): vis = visual @ visu_w^T + visu_b -> bf16 x[:,320:384]
    gemm_tf32<64, 64><<<dim3(1, BATCH / 64), 256, SM_TF, s1>>>(
        visual, VISD, visu_w, visu_b, xhp, 384, 320, VISD);

    // branch 2 (s2): weight conversion
    conv_w_kernel<<<448, 256, 0, s2>>>(w1, w2);

    // main stream: embeddings + FM
    embed_fm_kernel<<<BATCH / 4, 256>>>(uid, hour, scale, gender, age, attribute,
                                        user_emb, hour_emb, gender_emb, age_emb,
                                        attr_emb, fm_w, fm_b);

    cudaEventRecord(ev1, s1);
    cudaEventRecord(ev2, s2);
    cudaStreamWaitEvent(0, ev1, 0);
    cudaStreamWaitEvent(0, ev2, 0);

    // h1 = relu(x @ w1^T + b1)
    gemm_bf16k<128, 128><<<dim3(HID / 128, BATCH / 128), 256, SM_BF>>>(
        xhp, 384, w1p, b1, h1p, HID, 384);

    // h2 (registers only) -> logit partials
    gemm_bf16_last<128, 128><<<dim3(HID / 128, BATCH / 128), 256, SM_BF>>>(
        h1p, HID, w2p, b2, w3, HID);

    // softmax(fm + b3 + sum partials)
    softmax_kernel<<<BATCH / 256, 256>>>(b3, out);

    cudaEventDestroy(ev0);
    cudaEventDestroy(ev1);
    cudaEventDestroy(ev2);
    cudaStreamDestroy(s1);
    cudaStreamDestroy(s2);
}

// round 8
// speedup vs baseline: 1.3978x; 1.1979x over previous
#include <cuda_runtime.h>
#include <cuda_bf16.h>
#include <cstdint>
#include <math.h>

#define BATCH   16384
#define FK      64
#define VISD    2048
#define HID     512
#define NUSERS  1000000
#define VOCAB   (NUSERS + 24 + 2 + 8 + 40)

// Scratch (allocation-free rule: __device__ globals)
__device__ __nv_bfloat16 g_xh [BATCH * 384];
__device__ __nv_bfloat16 g_h1h[BATCH * HID];
__device__ __nv_bfloat16 g_w1h[HID * 384];
__device__ __nv_bfloat16 g_w2h[HID * HID];
__device__ float         g_fm [BATCH * 2];
__device__ float2        g_part[BATCH * 8];

// ---------------------------------------------------------------------------
// helpers (portable PTX only — harness targets compute_103, no 'a' features)
// ---------------------------------------------------------------------------
__device__ __forceinline__ uint32_t smem_u32(const void* p) {
    uint32_t a;
    asm("{ .reg .u64 t; cvta.to.shared.u64 t, %1; cvt.u32.u64 %0, t; }"
        : "=r"(a) : "l"(p));
    return a;
}
__device__ __forceinline__ void cp16(uint32_t s, const void* g) {
    asm volatile("cp.async.cg.shared.global [%0], [%1], 16;" :: "r"(s), "l"(g));
}
__device__ __forceinline__ void cp_commit() {
    asm volatile("cp.async.commit_group;" ::: "memory");
}
template<int N> __device__ __forceinline__ void cp_wait() {
    asm volatile("cp.async.wait_group %0;" :: "n"(N) : "memory");
}
__device__ __forceinline__ void ldsm4(uint32_t r[4], uint32_t addr) {
    asm volatile("ldmatrix.sync.aligned.m8n8.x4.shared.b16 {%0,%1,%2,%3}, [%4];"
        : "=r"(r[0]), "=r"(r[1]), "=r"(r[2]), "=r"(r[3]) : "r"(addr));
}
__device__ __forceinline__ void mma_tf32(float d[4], const uint32_t a[4],
                                         const uint32_t b[2]) {
    asm volatile(
        "mma.sync.aligned.m16n8k8.row.col.f32.tf32.tf32.f32 "
        "{%0,%1,%2,%3}, {%4,%5,%6,%7}, {%8,%9}, {%0,%1,%2,%3};"
        : "+f"(d[0]), "+f"(d[1]), "+f"(d[2]), "+f"(d[3])
        : "r"(a[0]), "r"(a[1]), "r"(a[2]), "r"(a[3]), "r"(b[0]), "r"(b[1]));
}
__device__ __forceinline__ void mma_bf16(float d[4], const uint32_t a[4],
                                         const uint32_t b[2]) {
    asm volatile(
        "mma.sync.aligned.m16n8k16.row.col.f32.bf16.bf16.f32 "
        "{%0,%1,%2,%3}, {%4,%5,%6,%7}, {%8,%9}, {%0,%1,%2,%3};"
        : "+f"(d[0]), "+f"(d[1]), "+f"(d[2]), "+f"(d[3])
        : "r"(a[0]), "r"(a[1]), "r"(a[2]), "r"(a[3]), "r"(b[0]), "r"(b[1]));
}
__device__ __forceinline__ uint32_t pack_bf16(float lo, float hi) {
    uint32_t r;
    asm("cvt.rn.bf16x2.f32 %0, %1, %2;" : "=r"(r) : "f"(hi), "f"(lo));
    return r;
}

// ---------------------------------------------------------------------------
// Weight conversion: w1, w2 fp32 -> bf16
// ---------------------------------------------------------------------------
__global__ void conv_w_kernel(const float* __restrict__ w1,
                              const float* __restrict__ w2)
{
    const int N1 = HID * 384 / 4;
    int i = blockIdx.x * blockDim.x + threadIdx.x;
    if (i < N1) {
        float4 v = ((const float4*)w1)[i];
        uint2 o = { pack_bf16(v.x, v.y), pack_bf16(v.z, v.w) };
        ((uint2*)g_w1h)[i] = o;
    } else {
        int j = i - N1;
        float4 v = ((const float4*)w2)[j];
        uint2 o = { pack_bf16(v.x, v.y), pack_bf16(v.z, v.w) };
        ((uint2*)g_w2h)[j] = o;
    }
}

// ---------------------------------------------------------------------------
// tf32 GEMM (vis): 64x64 tile, 4-stage cp.async, single sync, ldmatrix frags.
// ---------------------------------------------------------------------------
__global__ __launch_bounds__(256, 2) void gemm_tf32_vis(
    const float* __restrict__ A,
    const float* __restrict__ W,
    const float* __restrict__ bias,
    __nv_bfloat16* __restrict__ C)
{
    constexpr int BM = 64, BN = 64, BK = 32, S = 4;
    constexpr int LDT = 36;
    constexpr int WM = 2, WN = 4, TN = 2;
    constexpr int ASZ = BM * LDT;
    constexpr int WSZ = BN * LDT;

    extern __shared__ float sm[];
    float* sA = sm;                         // [S][ASZ]
    float* sW = sm + S * ASZ;               // [S][WSZ]
    __shared__ float sbias[BN];

    const int tid = threadIdx.x;
    const int m0  = blockIdx.x * BM;
    const int NC  = VISD / BK;

    if (tid < BN) sbias[tid] = bias[tid];

    const uint32_t sAu = smem_u32(sA);
    const uint32_t sWu = smem_u32(sW);

    auto load_tiles = [&](int c) {
        const int st = c % S;
        const int k0 = c * BK;
        #pragma unroll
        for (int j = 0; j < BM / 32; j++) {
            int i = tid + j * 256;
            int r = i >> 3, sg = i & 7;
            cp16(sAu + (st * ASZ + r * LDT) * 4 + sg * 16,
                 A + (size_t)(m0 + r) * VISD + k0 + sg * 4);
        }
        #pragma unroll
        for (int j = 0; j < BN / 32; j++) {
            int i = tid + j * 256;
            int r = i >> 3, sg = i & 7;
            cp16(sWu + (st * WSZ + r * LDT) * 4 + sg * 16,
                 W + (size_t)r * VISD + k0 + sg * 4);
        }
    };

    const int lane = tid & 31, warp = tid >> 5;
    const int g = lane >> 2, t = lane & 3;
    const int wm = warp % WM, wn = warp / WM;
    const int mbase = wm * 32;
    const int nbase = wn * (BN / WN);

    // ldmatrix per-lane address components
    const uint32_t rowA  = ((lane >> 3) & 1) * 8 + (lane & 7);
    const uint32_t abyte = (lane >> 4) * 16;
    const uint32_t rowB  = ((lane >> 4) << 3) + (lane & 7);
    const uint32_t bbyte = ((lane >> 3) & 1) * 16;

    float acc[2][TN][4] = {};

    load_tiles(0); cp_commit();
    load_tiles(1); cp_commit();
    load_tiles(2); cp_commit();

    for (int c = 0; c < NC; c++) {
        cp_wait<2>();
        __syncthreads();
        if (c + 3 < NC) load_tiles(c + 3);
        cp_commit();

        const uint32_t stA = sAu + (c % S) * ASZ * 4;
        const uint32_t stW = sWu + (c % S) * WSZ * 4;

        #pragma unroll
        for (int ks = 0; ks < 4; ks++) {
            uint32_t af[2][4], bf4[4];
            #pragma unroll
            for (int tm = 0; tm < 2; tm++)
                ldsm4(af[tm], stA + (mbase + tm * 16 + rowA) * (LDT * 4)
                              + ks * 32 + abyte);
            ldsm4(bf4, stW + (nbase + rowB) * (LDT * 4) + ks * 32 + bbyte);
            #pragma unroll
            for (int tm = 0; tm < 2; tm++) {
                mma_tf32(acc[tm][0], af[tm], bf4 + 0);
                mma_tf32(acc[tm][1], af[tm], bf4 + 2);
            }
        }
    }

    #pragma unroll
    for (int tm = 0; tm < 2; tm++) {
        #pragma unroll
        for (int tn = 0; tn < TN; tn++) {
            const int ncol = nbase + tn * 8 + 2 * t;
            const float b0 = sbias[ncol], b1 = sbias[ncol + 1];
            #pragma unroll
            for (int half = 0; half < 2; half++) {
                const int row = m0 + mbase + tm * 16 + g + half * 8;
                float vx = acc[tm][tn][half * 2 + 0] + b0;
                float vy = acc[tm][tn][half * 2 + 1] + b1;
                *(uint32_t*)(g_xh + (size_t)row * 384 + 320 + ncol) =
                    pack_bf16(vx, vy);
            }
        }
    }
}

// ---------------------------------------------------------------------------
// bf16 GEMM core pieces shared by mlp1 / mlp2-last (128x128, 3-stage, ldmatrix)
// ---------------------------------------------------------------------------
#define MLP_DECL                                                              \
    constexpr int BK = 32, S = 3, LDW = 20;                                   \
    constexpr int WM = 4, WN = 2, TN = 8;                                     \
    constexpr int BM = 128, BN = 128;                                         \
    constexpr int ASZ = BM * LDW;                                             \
    constexpr int WSZ = BN * LDW;                                             \
    (void)0

#define MLP_LOADER(Aptr, lda, Wptr, Kdim)                                     \
    auto load_tiles = [&](int c) {                                            \
        const int st = c % S;                                                 \
        const int k0 = c * BK;                                                \
        _Pragma("unroll")                                                     \
        for (int j = 0; j < BM / 64; j++) {                                   \
            int i = tid + j * 256;                                            \
            int r = i >> 2, sg = i & 3;                                       \
            cp16(sAu + (st * ASZ + r * LDW + sg * 4) * 4,                     \
                 Aptr + (size_t)(m0 + r) * lda + k0 + sg * 8);                \
        }                                                                     \
        _Pragma("unroll")                                                     \
        for (int j = 0; j < BN / 64; j++) {                                   \
            int i = tid + j * 256;                                            \
            int r = i >> 2, sg = i & 3;                                       \
            cp16(sWu + (st * WSZ + r * LDW + sg * 4) * 4,                     \
                 Wptr + (size_t)(n0 + r) * Kdim + k0 + sg * 8);               \
        }                                                                     \
    }

#define MLP_MAINLOOP(NC)                                                      \
    load_tiles(0); cp_commit();                                               \
    load_tiles(1); cp_commit();                                               \
    for (int c = 0; c < (NC); c++) {                                          \
        cp_wait<1>();                                                         \
        __syncthreads();                                                      \
        if (c + 2 < (NC)) load_tiles(c + 2);                                  \
        cp_commit();                                                          \
        const uint32_t stA = sAu + (c % S) * ASZ * 4;                         \
        const uint32_t stW = sWu + (c % S) * WSZ * 4;                         \
        _Pragma("unroll")                                                     \
        for (int ks = 0; ks < 2; ks++) {                                      \
            uint32_t af[2][4], bf[4][4];                                      \
            _Pragma("unroll")                                                 \
            for (int tm = 0; tm < 2; tm++)                                    \
                ldsm4(af[tm], stA + (mbase + tm * 16 + rowA) * (LDW * 4)      \
                              + ks * 32 + abyte);                             \
            _Pragma("unroll")                                                 \
            for (int p = 0; p < 4; p++)                                       \
                ldsm4(bf[p], stW + (nbase + p * 16 + rowB) * (LDW * 4)        \
                              + ks * 32 + bbyte);                             \
            _Pragma("unroll")                                                 \
            for (int tm = 0; tm < 2; tm++)                                    \
                _Pragma("unroll")                                             \
                for (int p = 0; p < 4; p++) {                                 \
                    mma_bf16(acc[tm][2 * p],     af[tm], bf[p] + 0);          \
                    mma_bf16(acc[tm][2 * p + 1], af[tm], bf[p] + 2);          \
                }                                                             \
        }                                                                     \
    }

#define MLP_COMMON_IDX                                                        \
    const int lane = tid & 31, warp = tid >> 5;                               \
    const int g = lane >> 2, t = lane & 3;                                    \
    const int wm = warp % WM, wn = warp / WM;                                 \
    const int mbase = wm * 32;                                                \
    const int nbase = wn * (BN / WN);                                         \
    const uint32_t rowA  = ((lane >> 3) & 1) * 8 + (lane & 7);                \
    const uint32_t abyte = (lane >> 4) * 16;                                  \
    const uint32_t rowB  = ((lane >> 4) << 3) + (lane & 7);                   \
    const uint32_t bbyte = ((lane >> 3) & 1) * 16

// ---------------------------------------------------------------------------
// mlp1: h1 = relu(x @ w1^T + b1) -> bf16
// ---------------------------------------------------------------------------
__global__ __launch_bounds__(256, 2) void gemm_mlp1(
    const __nv_bfloat16* __restrict__ A,
    const __nv_bfloat16* __restrict__ W,
    const float* __restrict__ bias,
    __nv_bfloat16* __restrict__ C)
{
    MLP_DECL;
    extern __shared__ uint32_t smw[];
    uint32_t* sA = smw;
    uint32_t* sW = smw + S * ASZ;
    __shared__ float sbias[BN];

    const int tid = threadIdx.x;
    const int m0  = blockIdx.y * BM;
    const int n0  = blockIdx.x * BN;

    if (tid < BN) sbias[tid] = bias[n0 + tid];

    const uint32_t sAu = smem_u32(sA);
    const uint32_t sWu = smem_u32(sW);
    MLP_LOADER(A, 384, W, 384);
    MLP_COMMON_IDX;

    float acc[2][TN][4] = {};
    MLP_MAINLOOP(384 / BK);

    #pragma unroll
    for (int tm = 0; tm < 2; tm++) {
        #pragma unroll
        for (int tn = 0; tn < TN; tn++) {
            const int ncol = nbase + tn * 8 + 2 * t;
            const float b0 = sbias[ncol], b1 = sbias[ncol + 1];
            const int gcol = n0 + ncol;
            #pragma unroll
            for (int half = 0; half < 2; half++) {
                const int row = m0 + mbase + tm * 16 + g + half * 8;
                float vx = fmaxf(acc[tm][tn][half * 2 + 0] + b0, 0.f);
                float vy = fmaxf(acc[tm][tn][half * 2 + 1] + b1, 0.f);
                *(uint32_t*)(C + (size_t)row * HID + gcol) = pack_bf16(vx, vy);
            }
        }
    }
}

// ---------------------------------------------------------------------------
// mlp2 + fused logits: h2 in regs only -> per-block logit partials
// ---------------------------------------------------------------------------
__global__ __launch_bounds__(256, 2) void gemm_mlp2_last(
    const __nv_bfloat16* __restrict__ A,
    const __nv_bfloat16* __restrict__ W,
    const float* __restrict__ bias,
    const float* __restrict__ w3)
{
    MLP_DECL;
    extern __shared__ uint32_t smw[];
    uint32_t* sA = smw;
    uint32_t* sW = smw + S * ASZ;
    __shared__ float sbias[BN];
    __shared__ float w3s[2][BN];

    const int tid = threadIdx.x;
    const int m0  = blockIdx.y * BM;
    const int n0  = blockIdx.x * BN;

    if (tid < BN) {
        sbias[tid]  = bias[n0 + tid];
        w3s[0][tid] = w3[n0 + tid];
        w3s[1][tid] = w3[HID + n0 + tid];
    }

    const uint32_t sAu = smem_u32(sA);
    const uint32_t sWu = smem_u32(sW);
    MLP_LOADER(A, HID, W, HID);
    MLP_COMMON_IDX;

    float acc[2][TN][4] = {};
    MLP_MAINLOOP(HID / BK);

    const int pidx = blockIdx.x * 2 + wn;
    #pragma unroll
    for (int tm = 0; tm < 2; tm++) {
        #pragma unroll
        for (int half = 0; half < 2; half++) {
            const int row = m0 + mbase + tm * 16 + g + half * 8;
            float s0 = 0.f, s1 = 0.f;
            #pragma unroll
            for (int tn = 0; tn < TN; tn++) {
                const int ncol = nbase + tn * 8 + 2 * t;
                float v0 = fmaxf(acc[tm][tn][half * 2 + 0] + sbias[ncol],     0.f);
                float v1 = fmaxf(acc[tm][tn][half * 2 + 1] + sbias[ncol + 1], 0.f);
                s0 = fmaf(v0, w3s[0][ncol], fmaf(v1, w3s[0][ncol + 1], s0));
                s1 = fmaf(v0, w3s[1][ncol], fmaf(v1, w3s[1][ncol + 1], s1));
            }
            s0 += __shfl_xor_sync(0xffffffffu, s0, 1);
            s0 += __shfl_xor_sync(0xffffffffu, s0, 2);
            s1 += __shfl_xor_sync(0xffffffffu, s1, 1);
            s1 += __shfl_xor_sync(0xffffffffu, s1, 2);
            if (t == 0)
                g_part[row * 8 + pidx] = make_float2(s0, s1);
        }
    }
}

// ---------------------------------------------------------------------------
// Embeddings + FM (1st + 2nd order) -> g_xh[:, 0:320], g_fm
// ---------------------------------------------------------------------------
__global__ void embed_fm_kernel(
    const int* __restrict__ uid, const int* __restrict__ hour,
    const float* __restrict__ scale,
    const int* __restrict__ gender, const int* __restrict__ age,
    const int* __restrict__ attr,
    const float* __restrict__ user_emb, const float* __restrict__ hour_emb,
    const float* __restrict__ gender_emb, const float* __restrict__ age_emb,
    const float* __restrict__ attr_emb,
    const float* __restrict__ fm_w, const float* __restrict__ fm_b)
{
    int s = threadIdx.x >> 6;
    int k = threadIdx.x & 63;
    int b = blockIdx.x * 4 + s;

    int u  = uid[b];
    int h  = hour[b];
    int g  = gender[b];
    int a  = age[b];
    int at = attr[b];
    float sc = scale[b];

    float e0 = user_emb[(size_t)u * 64 + k];
    float e1 = hour_emb[h * 64 + k];
    float e2 = sc * tanhf(gender_emb[g * 64 + k]);
    float e3 = sc * tanhf(attr_emb[at * 64 + k]);
    float e4 = sc * tanhf(age_emb[a * 64 + k]);

    __nv_bfloat16* xb = g_xh + (size_t)b * 384;
    xb[      k] = __float2bfloat16_rn(e0);
    xb[ 64 + k] = __float2bfloat16_rn(e1);
    xb[128 + k] = __float2bfloat16_rn(e2);
    xb[192 + k] = __float2bfloat16_rn(e3);
    xb[256 + k] = __float2bfloat16_rn(e4);

    float su = e0 + e1 + e2 + e3 + e4;
    float sq = e0*e0 + e1*e1 + e2*e2 + e3*e3 + e4*e4;
    float so = su * su - sq;

    #pragma unroll
    for (int o = 16; o > 0; o >>= 1)
        so += __shfl_down_sync(0xffffffffu, so, o);

    __shared__ float red[4][2];
    if ((k & 31) == 0) red[s][k >> 5] = so;
    __syncthreads();

    if (k == 0) {
        float second = 0.5f * (red[s][0] + red[s][1]);
        long c0 = u;
        long c1 = NUSERS + h;
        long c2 = NUSERS + 24 + g;
        long c3 = NUSERS + 26 + a;
        long c4 = NUSERS + 34 + at;
        #pragma unroll
        for (int j = 0; j < 2; j++) {
            const float* w = fm_w + (size_t)j * VOCAB;
            g_fm[b * 2 + j] =
                w[c0] + w[c1] + w[c2] + w[c3] + w[c4] + fm_b[j] + second;
        }
    }
}

// ---------------------------------------------------------------------------
// Softmax over (fm + b3 + sum of 8 partials), fixed summation order.
// ---------------------------------------------------------------------------
__global__ void softmax_kernel(const float* __restrict__ b3,
                               float* __restrict__ out)
{
    int b = blockIdx.x * 256 + threadIdx.x;
    float s0 = 0.f, s1 = 0.f;
    #pragma unroll
    for (int p = 0; p < 8; p++) {
        float2 v = g_part[b * 8 + p];
        s0 += v.x; s1 += v.y;
    }
    float l0 = g_fm[b * 2 + 0] + b3[0] + s0;
    float l1 = g_fm[b * 2 + 1] + b3[1] + s1;
    float m  = fmaxf(l0, l1);
    float e0 = expf(l0 - m), e1 = expf(l1 - m);
    float inv = 1.0f / (e0 + e1);
    out[b * 2 + 0] = e0 * inv;
    out[b * 2 + 1] = e1 * inv;
}

// ---------------------------------------------------------------------------
extern "C" void kernel_launch(void* const* d_in, const int* in_sizes, int n_in,
                              void* d_out, int out_size)
{
    const int*   uid        = (const int*)  d_in[0];
    const int*   hour       = (const int*)  d_in[1];
    const float* visual     = (const float*)d_in[2];
    const float* scale      = (const float*)d_in[3];
    const int*   gender     = (const int*)  d_in[4];
    const int*   age        = (const int*)  d_in[5];
    const int*   attribute  = (const int*)  d_in[6];
    const float* user_emb   = (const float*)d_in[7];
    const float* hour_emb   = (const float*)d_in[8];
    const float* gender_emb = (const float*)d_in[9];
    const float* age_emb    = (const float*)d_in[10];
    const float* attr_emb   = (const float*)d_in[11];
    const float* visu_w     = (const float*)d_in[12];
    const float* visu_b     = (const float*)d_in[13];
    const float* fm_w       = (const float*)d_in[14];
    const float* fm_b       = (const float*)d_in[15];
    const float* w1         = (const float*)d_in[16];
    const float* b1         = (const float*)d_in[17];
    const float* w2         = (const float*)d_in[18];
    const float* b2         = (const float*)d_in[19];
    const float* w3         = (const float*)d_in[20];
    const float* b3         = (const float*)d_in[21];
    float* out = (float*)d_out;

    __nv_bfloat16 *xhp, *h1p, *w1p, *w2p;
    cudaGetSymbolAddress((void**)&xhp, g_xh);
    cudaGetSymbolAddress((void**)&h1p, g_h1h);
    cudaGetSymbolAddress((void**)&w1p, g_w1h);
    cudaGetSymbolAddress((void**)&w2p, g_w2h);

    const int SM_VIS = 4 * (64 + 64) * 36 * 4;           // 73,728 B
    const int SM_MLP = 3 * (128 + 128) * 20 * 4;         // 61,440 B
    cudaFuncSetAttribute(gemm_tf32_vis,  cudaFuncAttributeMaxDynamicSharedMemorySize, SM_VIS);
    cudaFuncSetAttribute(gemm_mlp1,      cudaFuncAttributeMaxDynamicSharedMemorySize, SM_MLP);
    cudaFuncSetAttribute(gemm_mlp2_last, cudaFuncAttributeMaxDynamicSharedMemorySize, SM_MLP);

    // fork two side branches off the capture stream
    cudaStream_t s1, s2;
    cudaStreamCreateWithFlags(&s1, cudaStreamNonBlocking);
    cudaStreamCreateWithFlags(&s2, cudaStreamNonBlocking);
    cudaEvent_t ev0, ev1, ev2;
    cudaEventCreateWithFlags(&ev0, cudaEventDisableTiming);
    cudaEventCreateWithFlags(&ev1, cudaEventDisableTiming);
    cudaEventCreateWithFlags(&ev2, cudaEventDisableTiming);

    cudaEventRecord(ev0, 0);
    cudaStreamWaitEvent(s1, ev0, 0);
    cudaStreamWaitEvent(s2, ev0, 0);

    // branch 1 (s1): vis = visual @ visu_w^T + visu_b -> bf16 x[:,320:384]
    gemm_tf32_vis<<<BATCH / 64, 256, SM_VIS, s1>>>(visual, visu_w, visu_b, xhp);

    // branch 2 (s2): weight conversion
    conv_w_kernel<<<448, 256, 0, s2>>>(w1, w2);

    // main stream: embeddings + FM
    embed_fm_kernel<<<BATCH / 4, 256>>>(uid, hour, scale, gender, age, attribute,
                                        user_emb, hour_emb, gender_emb, age_emb,
                                        attr_emb, fm_w, fm_b);

    cudaEventRecord(ev1, s1);
    cudaEventRecord(ev2, s2);
    cudaStreamWaitEvent(0, ev1, 0);
    cudaStreamWaitEvent(0, ev2, 0);

    // h1 = relu(x @ w1^T + b1)
    gemm_mlp1<<<dim3(HID / 128, BATCH / 128), 256, SM_MLP>>>(xhp, w1p, b1, h1p);

    // h2 (registers only) -> logit partials
    gemm_mlp2_last<<<dim3(HID / 128, BATCH / 128), 256, SM_MLP>>>(h1p, w2p, b2, w3);

    // softmax(fm + b3 + sum partials)
    softmax_kernel<<<BATCH / 256, 256>>>(b3, out);

    cudaEventDestroy(ev0);
    cudaEventDestroy(ev1);
    cudaEventDestroy(ev2);
    cudaStreamDestroy(s1);
    cudaStreamDestroy(s2);
}

// round 9
// speedup vs baseline: 1.4208x; 1.0165x over previous
#include <cuda_runtime.h>
#include <cuda_bf16.h>
#include <cstdint>
#include <math.h>

#define BATCH   16384
#define FK      64
#define VISD    2048
#define HID     512
#define NUSERS  1000000
#define VOCAB   (NUSERS + 24 + 2 + 8 + 40)

// Scratch (allocation-free rule: __device__ globals)
__device__ __nv_bfloat16 g_xh [BATCH * 384];
__device__ __nv_bfloat16 g_h1h[BATCH * HID];
__device__ __nv_bfloat16 g_w1h[HID * 384];
__device__ __nv_bfloat16 g_w2h[HID * HID];
__device__ float         g_fm [BATCH * 2];
__device__ float2        g_part[BATCH * 4];

// ---------------------------------------------------------------------------
// helpers (portable PTX only — harness targets compute_103, no 'a' features)
// ---------------------------------------------------------------------------
__device__ __forceinline__ uint32_t smem_u32(const void* p) {
    uint32_t a;
    asm("{ .reg .u64 t; cvta.to.shared.u64 t, %1; cvt.u32.u64 %0, t; }"
        : "=r"(a) : "l"(p));
    return a;
}
__device__ __forceinline__ void cp16(uint32_t s, const void* g) {
    asm volatile("cp.async.cg.shared.global [%0], [%1], 16;" :: "r"(s), "l"(g));
}
__device__ __forceinline__ void cp_commit() {
    asm volatile("cp.async.commit_group;" ::: "memory");
}
template<int N> __device__ __forceinline__ void cp_wait() {
    asm volatile("cp.async.wait_group %0;" :: "n"(N) : "memory");
}
__device__ __forceinline__ void ldsm4(uint32_t r[4], uint32_t addr) {
    asm volatile("ldmatrix.sync.aligned.m8n8.x4.shared.b16 {%0,%1,%2,%3}, [%4];"
        : "=r"(r[0]), "=r"(r[1]), "=r"(r[2]), "=r"(r[3]) : "r"(addr));
}
__device__ __forceinline__ void mma_tf32(float d[4], const uint32_t a[4],
                                         const uint32_t b[2]) {
    asm volatile(
        "mma.sync.aligned.m16n8k8.row.col.f32.tf32.tf32.f32 "
        "{%0,%1,%2,%3}, {%4,%5,%6,%7}, {%8,%9}, {%0,%1,%2,%3};"
        : "+f"(d[0]), "+f"(d[1]), "+f"(d[2]), "+f"(d[3])
        : "r"(a[0]), "r"(a[1]), "r"(a[2]), "r"(a[3]), "r"(b[0]), "r"(b[1]));
}
__device__ __forceinline__ void mma_bf16(float d[4], const uint32_t a[4],
                                         const uint32_t b[2]) {
    asm volatile(
        "mma.sync.aligned.m16n8k16.row.col.f32.bf16.bf16.f32 "
        "{%0,%1,%2,%3}, {%4,%5,%6,%7}, {%8,%9}, {%0,%1,%2,%3};"
        : "+f"(d[0]), "+f"(d[1]), "+f"(d[2]), "+f"(d[3])
        : "r"(a[0]), "r"(a[1]), "r"(a[2]), "r"(a[3]), "r"(b[0]), "r"(b[1]));
}
__device__ __forceinline__ uint32_t pack_bf16(float lo, float hi) {
    uint32_t r;
    asm("cvt.rn.bf16x2.f32 %0, %1, %2;" : "=r"(r) : "f"(hi), "f"(lo));
    return r;
}

// ---------------------------------------------------------------------------
// Weight conversion: w1, w2 fp32 -> bf16
// ---------------------------------------------------------------------------
__global__ void conv_w_kernel(const float* __restrict__ w1,
                              const float* __restrict__ w2)
{
    const int N1 = HID * 384 / 4;
    int i = blockIdx.x * blockDim.x + threadIdx.x;
    if (i < N1) {
        float4 v = ((const float4*)w1)[i];
        uint2 o = { pack_bf16(v.x, v.y), pack_bf16(v.z, v.w) };
        ((uint2*)g_w1h)[i] = o;
    } else {
        int j = i - N1;
        float4 v = ((const float4*)w2)[j];
        uint2 o = { pack_bf16(v.x, v.y), pack_bf16(v.z, v.w) };
        ((uint2*)g_w2h)[j] = o;
    }
}

// ---------------------------------------------------------------------------
// tf32 GEMM (vis): 64x64 tile, 4-stage cp.async, ldmatrix frags (proven R8).
// ---------------------------------------------------------------------------
__global__ __launch_bounds__(256, 2) void gemm_tf32_vis(
    const float* __restrict__ A,
    const float* __restrict__ W,
    const float* __restrict__ bias,
    __nv_bfloat16* __restrict__ C)
{
    constexpr int BM = 64, BN = 64, BK = 32, S = 4;
    constexpr int LDT = 36;
    constexpr int WM = 2, WN = 4, TN = 2;
    constexpr int ASZ = BM * LDT;
    constexpr int WSZ = BN * LDT;

    extern __shared__ float sm[];
    float* sA = sm;
    float* sW = sm + S * ASZ;
    __shared__ float sbias[BN];

    const int tid = threadIdx.x;
    const int m0  = blockIdx.x * BM;
    const int NC  = VISD / BK;

    if (tid < BN) sbias[tid] = bias[tid];

    const uint32_t sAu = smem_u32(sA);
    const uint32_t sWu = smem_u32(sW);

    auto load_tiles = [&](int c) {
        const int st = c % S;
        const int k0 = c * BK;
        #pragma unroll
        for (int j = 0; j < BM / 32; j++) {
            int i = tid + j * 256;
            int r = i >> 3, sg = i & 7;
            cp16(sAu + (st * ASZ + r * LDT) * 4 + sg * 16,
                 A + (size_t)(m0 + r) * VISD + k0 + sg * 4);
        }
        #pragma unroll
        for (int j = 0; j < BN / 32; j++) {
            int i = tid + j * 256;
            int r = i >> 3, sg = i & 7;
            cp16(sWu + (st * WSZ + r * LDT) * 4 + sg * 16,
                 W + (size_t)r * VISD + k0 + sg * 4);
        }
    };

    const int lane = tid & 31, warp = tid >> 5;
    const int g = lane >> 2, t = lane & 3;
    const int wm = warp % WM, wn = warp / WM;
    const int mbase = wm * 32;
    const int nbase = wn * (BN / WN);

    const uint32_t rowA  = ((lane >> 3) & 1) * 8 + (lane & 7);
    const uint32_t abyte = (lane >> 4) * 16;
    const uint32_t rowB  = ((lane >> 4) << 3) + (lane & 7);
    const uint32_t bbyte = ((lane >> 3) & 1) * 16;

    float acc[2][TN][4] = {};

    load_tiles(0); cp_commit();
    load_tiles(1); cp_commit();
    load_tiles(2); cp_commit();

    for (int c = 0; c < NC; c++) {
        cp_wait<2>();
        __syncthreads();
        if (c + 3 < NC) load_tiles(c + 3);
        cp_commit();

        const uint32_t stA = sAu + (c % S) * ASZ * 4;
        const uint32_t stW = sWu + (c % S) * WSZ * 4;

        #pragma unroll
        for (int ks = 0; ks < 4; ks++) {
            uint32_t af[2][4], bf4[4];
            #pragma unroll
            for (int tm = 0; tm < 2; tm++)
                ldsm4(af[tm], stA + (mbase + tm * 16 + rowA) * (LDT * 4)
                              + ks * 32 + abyte);
            ldsm4(bf4, stW + (nbase + rowB) * (LDT * 4) + ks * 32 + bbyte);
            #pragma unroll
            for (int tm = 0; tm < 2; tm++) {
                mma_tf32(acc[tm][0], af[tm], bf4 + 0);
                mma_tf32(acc[tm][1], af[tm], bf4 + 2);
            }
        }
    }

    #pragma unroll
    for (int tm = 0; tm < 2; tm++) {
        #pragma unroll
        for (int tn = 0; tn < TN; tn++) {
            const int ncol = nbase + tn * 8 + 2 * t;
            const float b0 = sbias[ncol], b1 = sbias[ncol + 1];
            #pragma unroll
            for (int half = 0; half < 2; half++) {
                const int row = m0 + mbase + tm * 16 + g + half * 8;
                float vx = acc[tm][tn][half * 2 + 0] + b0;
                float vy = acc[tm][tn][half * 2 + 1] + b1;
                *(uint32_t*)(g_xh + (size_t)row * 384 + 320 + ncol) =
                    pack_bf16(vx, vy);
            }
        }
    }
}

// ---------------------------------------------------------------------------
// MLP bf16 GEMM: 128-thread CTA (4 warps), warp tile 32x128, ~240 regs/thread.
// BM=BN=128, BK=32, 3-stage cp.async, single barrier per iteration.
// ---------------------------------------------------------------------------
#define MLP_DECL                                                              \
    constexpr int BK = 32, S = 3, LDW = 20;                                   \
    constexpr int BM = 128, BN = 128, TN = 16;                                \
    constexpr int ASZ = BM * LDW;                                             \
    constexpr int WSZ = BN * LDW;                                             \
    (void)0

#define MLP_LOADER(Aptr, lda, Wptr, Kdim)                                     \
    auto load_tiles = [&](int c) {                                            \
        const int st = c % S;                                                 \
        const int k0 = c * BK;                                                \
        _Pragma("unroll")                                                     \
        for (int j = 0; j < 4; j++) {                                         \
            int i = tid + j * 128;                                            \
            int r = i >> 2, sg = i & 3;                                       \
            cp16(sAu + (st * ASZ + r * LDW + sg * 4) * 4,                     \
                 Aptr + (size_t)(m0 + r) * lda + k0 + sg * 8);                \
        }                                                                     \
        _Pragma("unroll")                                                     \
        for (int j = 0; j < 4; j++) {                                         \
            int i = tid + j * 128;                                            \
            int r = i >> 2, sg = i & 3;                                       \
            cp16(sWu + (st * WSZ + r * LDW + sg * 4) * 4,                     \
                 Wptr + (size_t)(n0 + r) * Kdim + k0 + sg * 8);               \
        }                                                                     \
    }

#define MLP_COMMON_IDX                                                        \
    const int lane = tid & 31, warp = tid >> 5;                               \
    const int g = lane >> 2, t = lane & 3;                                    \
    const int mbase = warp * 32;                                              \
    const uint32_t rowA  = ((lane >> 3) & 1) * 8 + (lane & 7);                \
    const uint32_t abyte = (lane >> 4) * 16;                                  \
    const uint32_t rowB  = ((lane >> 4) << 3) + (lane & 7);                   \
    const uint32_t bbyte = ((lane >> 3) & 1) * 16

#define MLP_MAINLOOP(NC)                                                      \
    load_tiles(0); cp_commit();                                               \
    load_tiles(1); cp_commit();                                               \
    for (int c = 0; c < (NC); c++) {                                          \
        cp_wait<1>();                                                         \
        __syncthreads();                                                      \
        if (c + 2 < (NC)) load_tiles(c + 2);                                  \
        cp_commit();                                                          \
        const uint32_t stA = sAu + (c % S) * ASZ * 4;                         \
        const uint32_t stW = sWu + (c % S) * WSZ * 4;                         \
        _Pragma("unroll")                                                     \
        for (int ks = 0; ks < 2; ks++) {                                      \
            uint32_t af[2][4], bf[8][4];                                      \
            _Pragma("unroll")                                                 \
            for (int tm = 0; tm < 2; tm++)                                    \
                ldsm4(af[tm], stA + (mbase + tm * 16 + rowA) * (LDW * 4)      \
                              + ks * 32 + abyte);                             \
            _Pragma("unroll")                                                 \
            for (int p = 0; p < 8; p++)                                       \
                ldsm4(bf[p], stW + (p * 16 + rowB) * (LDW * 4)                \
                              + ks * 32 + bbyte);                             \
            _Pragma("unroll")                                                 \
            for (int tm = 0; tm < 2; tm++)                                    \
                _Pragma("unroll")                                             \
                for (int p = 0; p < 8; p++) {                                 \
                    mma_bf16(acc[tm][2 * p],     af[tm], bf[p] + 0);          \
                    mma_bf16(acc[tm][2 * p + 1], af[tm], bf[p] + 2);          \
                }                                                             \
        }                                                                     \
    }

// ---------------------------------------------------------------------------
// mlp1: h1 = relu(x @ w1^T + b1) -> bf16
// ---------------------------------------------------------------------------
__global__ __launch_bounds__(128, 2) void gemm_mlp1(
    const __nv_bfloat16* __restrict__ A,
    const __nv_bfloat16* __restrict__ W,
    const float* __restrict__ bias,
    __nv_bfloat16* __restrict__ C)
{
    MLP_DECL;
    extern __shared__ uint32_t smw[];
    uint32_t* sA = smw;
    uint32_t* sW = smw + S * ASZ;
    __shared__ float sbias[BN];

    const int tid = threadIdx.x;
    const int m0  = blockIdx.y * BM;
    const int n0  = blockIdx.x * BN;

    sbias[tid] = bias[n0 + tid];

    const uint32_t sAu = smem_u32(sA);
    const uint32_t sWu = smem_u32(sW);
    MLP_LOADER(A, 384, W, 384);
    MLP_COMMON_IDX;

    float acc[2][TN][4] = {};
    MLP_MAINLOOP(384 / BK);

    #pragma unroll
    for (int tm = 0; tm < 2; tm++) {
        #pragma unroll
        for (int tn = 0; tn < TN; tn++) {
            const int ncol = tn * 8 + 2 * t;
            const float b0 = sbias[ncol], b1 = sbias[ncol + 1];
            const int gcol = n0 + ncol;
            #pragma unroll
            for (int half = 0; half < 2; half++) {
                const int row = m0 + mbase + tm * 16 + g + half * 8;
                float vx = fmaxf(acc[tm][tn][half * 2 + 0] + b0, 0.f);
                float vy = fmaxf(acc[tm][tn][half * 2 + 1] + b1, 0.f);
                *(uint32_t*)(C + (size_t)row * HID + gcol) = pack_bf16(vx, vy);
            }
        }
    }
}

// ---------------------------------------------------------------------------
// mlp2 + fused logits: h2 in regs only -> per-block logit partials
// ---------------------------------------------------------------------------
__global__ __launch_bounds__(128, 2) void gemm_mlp2_last(
    const __nv_bfloat16* __restrict__ A,
    const __nv_bfloat16* __restrict__ W,
    const float* __restrict__ bias,
    const float* __restrict__ w3)
{
    MLP_DECL;
    extern __shared__ uint32_t smw[];
    uint32_t* sA = smw;
    uint32_t* sW = smw + S * ASZ;
    __shared__ float sbias[BN];
    __shared__ float w3s[2][BN];

    const int tid = threadIdx.x;
    const int m0  = blockIdx.y * BM;
    const int n0  = blockIdx.x * BN;

    sbias[tid]  = bias[n0 + tid];
    w3s[0][tid] = w3[n0 + tid];
    w3s[1][tid] = w3[HID + n0 + tid];

    const uint32_t sAu = smem_u32(sA);
    const uint32_t sWu = smem_u32(sW);
    MLP_LOADER(A, HID, W, HID);
    MLP_COMMON_IDX;

    float acc[2][TN][4] = {};
    MLP_MAINLOOP(HID / BK);

    #pragma unroll
    for (int tm = 0; tm < 2; tm++) {
        #pragma unroll
        for (int half = 0; half < 2; half++) {
            const int row = m0 + mbase + tm * 16 + g + half * 8;
            float s0 = 0.f, s1 = 0.f;
            #pragma unroll
            for (int tn = 0; tn < TN; tn++) {
                const int ncol = tn * 8 + 2 * t;
                float v0 = fmaxf(acc[tm][tn][half * 2 + 0] + sbias[ncol],     0.f);
                float v1 = fmaxf(acc[tm][tn][half * 2 + 1] + sbias[ncol + 1], 0.f);
                s0 = fmaf(v0, w3s[0][ncol], fmaf(v1, w3s[0][ncol + 1], s0));
                s1 = fmaf(v0, w3s[1][ncol], fmaf(v1, w3s[1][ncol + 1], s1));
            }
            s0 += __shfl_xor_sync(0xffffffffu, s0, 1);
            s0 += __shfl_xor_sync(0xffffffffu, s0, 2);
            s1 += __shfl_xor_sync(0xffffffffu, s1, 1);
            s1 += __shfl_xor_sync(0xffffffffu, s1, 2);
            if (t == 0)
                g_part[row * 4 + blockIdx.x] = make_float2(s0, s1);
        }
    }
}

// ---------------------------------------------------------------------------
// Embeddings + FM (1st + 2nd order) -> g_xh[:, 0:320], g_fm
// ---------------------------------------------------------------------------
__global__ void embed_fm_kernel(
    const int* __restrict__ uid, const int* __restrict__ hour,
    const float* __restrict__ scale,
    const int* __restrict__ gender, const int* __restrict__ age,
    const int* __restrict__ attr,
    const float* __restrict__ user_emb, const float* __restrict__ hour_emb,
    const float* __restrict__ gender_emb, const float* __restrict__ age_emb,
    const float* __restrict__ attr_emb,
    const float* __restrict__ fm_w, const float* __restrict__ fm_b)
{
    int s = threadIdx.x >> 6;
    int k = threadIdx.x & 63;
    int b = blockIdx.x * 4 + s;

    int u  = uid[b];
    int h  = hour[b];
    int g  = gender[b];
    int a  = age[b];
    int at = attr[b];
    float sc = scale[b];

    float e0 = user_emb[(size_t)u * 64 + k];
    float e1 = hour_emb[h * 64 + k];
    float e2 = sc * tanhf(gender_emb[g * 64 + k]);
    float e3 = sc * tanhf(attr_emb[at * 64 + k]);
    float e4 = sc * tanhf(age_emb[a * 64 + k]);

    __nv_bfloat16* xb = g_xh + (size_t)b * 384;
    xb[      k] = __float2bfloat16_rn(e0);
    xb[ 64 + k] = __float2bfloat16_rn(e1);
    xb[128 + k] = __float2bfloat16_rn(e2);
    xb[192 + k] = __float2bfloat16_rn(e3);
    xb[256 + k] = __float2bfloat16_rn(e4);

    float su = e0 + e1 + e2 + e3 + e4;
    float sq = e0*e0 + e1*e1 + e2*e2 + e3*e3 + e4*e4;
    float so = su * su - sq;

    #pragma unroll
    for (int o = 16; o > 0; o >>= 1)
        so += __shfl_down_sync(0xffffffffu, so, o);

    __shared__ float red[4][2];
    if ((k & 31) == 0) red[s][k >> 5] = so;
    __syncthreads();

    if (k == 0) {
        float second = 0.5f * (red[s][0] + red[s][1]);
        long c0 = u;
        long c1 = NUSERS + h;
        long c2 = NUSERS + 24 + g;
        long c3 = NUSERS + 26 + a;
        long c4 = NUSERS + 34 + at;
        #pragma unroll
        for (int j = 0; j < 2; j++) {
            const float* w = fm_w + (size_t)j * VOCAB;
            g_fm[b * 2 + j] =
                w[c0] + w[c1] + w[c2] + w[c3] + w[c4] + fm_b[j] + second;
        }
    }
}

// ---------------------------------------------------------------------------
// Softmax over (fm + b3 + sum of 4 partials), fixed summation order.
// ---------------------------------------------------------------------------
__global__ void softmax_kernel(const float* __restrict__ b3,
                               float* __restrict__ out)
{
    int b = blockIdx.x * 256 + threadIdx.x;
    float s0 = 0.f, s1 = 0.f;
    #pragma unroll
    for (int p = 0; p < 4; p++) {
        float2 v = g_part[b * 4 + p];
        s0 += v.x; s1 += v.y;
    }
    float l0 = g_fm[b * 2 + 0] + b3[0] + s0;
    float l1 = g_fm[b * 2 + 1] + b3[1] + s1;
    float m  = fmaxf(l0, l1);
    float e0 = expf(l0 - m), e1 = expf(l1 - m);
    float inv = 1.0f / (e0 + e1);
    out[b * 2 + 0] = e0 * inv;
    out[b * 2 + 1] = e1 * inv;
}

// ---------------------------------------------------------------------------
extern "C" void kernel_launch(void* const* d_in, const int* in_sizes, int n_in,
                              void* d_out, int out_size)
{
    const int*   uid        = (const int*)  d_in[0];
    const int*   hour       = (const int*)  d_in[1];
    const float* visual     = (const float*)d_in[2];
    const float* scale      = (const float*)d_in[3];
    const int*   gender     = (const int*)  d_in[4];
    const int*   age        = (const int*)  d_in[5];
    const int*   attribute  = (const int*)  d_in[6];
    const float* user_emb   = (const float*)d_in[7];
    const float* hour_emb   = (const float*)d_in[8];
    const float* gender_emb = (const float*)d_in[9];
    const float* age_emb    = (const float*)d_in[10];
    const float* attr_emb   = (const float*)d_in[11];
    const float* visu_w     = (const float*)d_in[12];
    const float* visu_b     = (const float*)d_in[13];
    const float* fm_w       = (const float*)d_in[14];
    const float* fm_b       = (const float*)d_in[15];
    const float* w1         = (const float*)d_in[16];
    const float* b1         = (const float*)d_in[17];
    const float* w2         = (const float*)d_in[18];
    const float* b2         = (const float*)d_in[19];
    const float* w3         = (const float*)d_in[20];
    const float* b3         = (const float*)d_in[21];
    float* out = (float*)d_out;

    __nv_bfloat16 *xhp, *h1p, *w1p, *w2p;
    cudaGetSymbolAddress((void**)&xhp, g_xh);
    cudaGetSymbolAddress((void**)&h1p, g_h1h);
    cudaGetSymbolAddress((void**)&w1p, g_w1h);
    cudaGetSymbolAddress((void**)&w2p, g_w2h);

    const int SM_VIS = 4 * (64 + 64) * 36 * 4;           // 73,728 B
    const int SM_MLP = 3 * (128 + 128) * 20 * 4;         // 61,440 B
    cudaFuncSetAttribute(gemm_tf32_vis,  cudaFuncAttributeMaxDynamicSharedMemorySize, SM_VIS);
    cudaFuncSetAttribute(gemm_mlp1,      cudaFuncAttributeMaxDynamicSharedMemorySize, SM_MLP);
    cudaFuncSetAttribute(gemm_mlp2_last, cudaFuncAttributeMaxDynamicSharedMemorySize, SM_MLP);

    // fork two side branches off the capture stream
    cudaStream_t s1, s2;
    cudaStreamCreateWithFlags(&s1, cudaStreamNonBlocking);
    cudaStreamCreateWithFlags(&s2, cudaStreamNonBlocking);
    cudaEvent_t ev0, ev1, ev2;
    cudaEventCreateWithFlags(&ev0, cudaEventDisableTiming);
    cudaEventCreateWithFlags(&ev1, cudaEventDisableTiming);
    cudaEventCreateWithFlags(&ev2, cudaEventDisableTiming);

    cudaEventRecord(ev0, 0);
    cudaStreamWaitEvent(s1, ev0, 0);
    cudaStreamWaitEvent(s2, ev0, 0);

    // branch 1 (s1): vis = visual @ visu_w^T + visu_b -> bf16 x[:,320:384]
    gemm_tf32_vis<<<BATCH / 64, 256, SM_VIS, s1>>>(visual, visu_w, visu_b, xhp);

    // branch 2 (s2): weight conversion
    conv_w_kernel<<<448, 256, 0, s2>>>(w1, w2);

    // main stream: embeddings + FM
    embed_fm_kernel<<<BATCH / 4, 256>>>(uid, hour, scale, gender, age, attribute,
                                        user_emb, hour_emb, gender_emb, age_emb,
                                        attr_emb, fm_w, fm_b);

    cudaEventRecord(ev1, s1);
    cudaEventRecord(ev2, s2);
    cudaStreamWaitEvent(0, ev1, 0);
    cudaStreamWaitEvent(0, ev2, 0);

    // h1 = relu(x @ w1^T + b1)  — 128-thread CTAs, high-ILP config
    gemm_mlp1<<<dim3(HID / 128, BATCH / 128), 128, SM_MLP>>>(xhp, w1p, b1, h1p);

    // h2 (registers only) -> logit partials
    gemm_mlp2_last<<<dim3(HID / 128, BATCH / 128), 128, SM_MLP>>>(h1p, w2p, b2, w3);

    // softmax(fm + b3 + sum partials)
    softmax_kernel<<<BATCH / 256, 256>>>(b3, out);

    cudaEventDestroy(ev0);
    cudaEventDestroy(ev1);
    cudaEventDestroy(ev2);
    cudaStreamDestroy(s1);
    cudaStreamDestroy(s2);
}

// round 10
// speedup vs baseline: 1.4212x; 1.0003x over previous
#include <cuda_runtime.h>
#include <cuda_bf16.h>
#include <cstdint>
#include <math.h>

#define BATCH   16384
#define FK      64
#define VISD    2048
#define HID     512
#define NUSERS  1000000
#define VOCAB   (NUSERS + 24 + 2 + 8 + 40)

// Scratch (allocation-free rule: __device__ globals)
__device__ __nv_bfloat16 g_xh [BATCH * 384];
__device__ __nv_bfloat16 g_h1h[BATCH * HID];
__device__ __nv_bfloat16 g_w1h[HID * 384];
__device__ __nv_bfloat16 g_w2h[HID * HID];
__device__ float         g_fm [BATCH * 2];
__device__ float2        g_part[BATCH * 4];

// ---------------------------------------------------------------------------
// helpers (portable PTX only — harness targets compute_103, no 'a' features)
// ---------------------------------------------------------------------------
__device__ __forceinline__ uint32_t smem_u32(const void* p) {
    uint32_t a;
    asm("{ .reg .u64 t; cvta.to.shared.u64 t, %1; cvt.u32.u64 %0, t; }"
        : "=r"(a) : "l"(p));
    return a;
}
__device__ __forceinline__ void cp16(uint32_t s, const void* g) {
    asm volatile("cp.async.cg.shared.global [%0], [%1], 16;" :: "r"(s), "l"(g));
}
__device__ __forceinline__ void cp_commit() {
    asm volatile("cp.async.commit_group;" ::: "memory");
}
template<int N> __device__ __forceinline__ void cp_wait() {
    asm volatile("cp.async.wait_group %0;" :: "n"(N) : "memory");
}
__device__ __forceinline__ void ldsm4(uint32_t r[4], uint32_t addr) {
    asm volatile("ldmatrix.sync.aligned.m8n8.x4.shared.b16 {%0,%1,%2,%3}, [%4];"
        : "=r"(r[0]), "=r"(r[1]), "=r"(r[2]), "=r"(r[3]) : "r"(addr));
}
__device__ __forceinline__ void mma_tf32(float d[4], const uint32_t a[4],
                                         const uint32_t b[2]) {
    asm volatile(
        "mma.sync.aligned.m16n8k8.row.col.f32.tf32.tf32.f32 "
        "{%0,%1,%2,%3}, {%4,%5,%6,%7}, {%8,%9}, {%0,%1,%2,%3};"
        : "+f"(d[0]), "+f"(d[1]), "+f"(d[2]), "+f"(d[3])
        : "r"(a[0]), "r"(a[1]), "r"(a[2]), "r"(a[3]), "r"(b[0]), "r"(b[1]));
}
__device__ __forceinline__ void mma_bf16(float d[4], const uint32_t a[4],
                                         const uint32_t b[2]) {
    asm volatile(
        "mma.sync.aligned.m16n8k16.row.col.f32.bf16.bf16.f32 "
        "{%0,%1,%2,%3}, {%4,%5,%6,%7}, {%8,%9}, {%0,%1,%2,%3};"
        : "+f"(d[0]), "+f"(d[1]), "+f"(d[2]), "+f"(d[3])
        : "r"(a[0]), "r"(a[1]), "r"(a[2]), "r"(a[3]), "r"(b[0]), "r"(b[1]));
}
__device__ __forceinline__ uint32_t pack_bf16(float lo, float hi) {
    uint32_t r;
    asm("cvt.rn.bf16x2.f32 %0, %1, %2;" : "=r"(r) : "f"(hi), "f"(lo));
    return r;
}

// ---------------------------------------------------------------------------
// Weight conversion: w1, w2 fp32 -> bf16
// ---------------------------------------------------------------------------
__global__ void conv_w_kernel(const float* __restrict__ w1,
                              const float* __restrict__ w2)
{
    const int N1 = HID * 384 / 4;
    int i = blockIdx.x * blockDim.x + threadIdx.x;
    if (i < N1) {
        float4 v = ((const float4*)w1)[i];
        uint2 o = { pack_bf16(v.x, v.y), pack_bf16(v.z, v.w) };
        ((uint2*)g_w1h)[i] = o;
    } else {
        int j = i - N1;
        float4 v = ((const float4*)w2)[j];
        uint2 o = { pack_bf16(v.x, v.y), pack_bf16(v.z, v.w) };
        ((uint2*)g_w2h)[j] = o;
    }
}

// ---------------------------------------------------------------------------
// tf32 GEMM (vis): 64x64 tile, 4-stage cp.async, ldmatrix frags (proven R8).
// ---------------------------------------------------------------------------
__global__ __launch_bounds__(256, 2) void gemm_tf32_vis(
    const float* __restrict__ A,
    const float* __restrict__ W,
    const float* __restrict__ bias,
    __nv_bfloat16* __restrict__ C)
{
    constexpr int BM = 64, BN = 64, BK = 32, S = 4;
    constexpr int LDT = 36;
    constexpr int WM = 2, WN = 4, TN = 2;
    constexpr int ASZ = BM * LDT;
    constexpr int WSZ = BN * LDT;

    extern __shared__ float sm[];
    float* sA = sm;
    float* sW = sm + S * ASZ;
    __shared__ float sbias[BN];

    const int tid = threadIdx.x;
    const int m0  = blockIdx.x * BM;
    const int NC  = VISD / BK;

    if (tid < BN) sbias[tid] = bias[tid];

    const uint32_t sAu = smem_u32(sA);
    const uint32_t sWu = smem_u32(sW);

    auto load_tiles = [&](int c) {
        const int st = c % S;
        const int k0 = c * BK;
        #pragma unroll
        for (int j = 0; j < BM / 32; j++) {
            int i = tid + j * 256;
            int r = i >> 3, sg = i & 7;
            cp16(sAu + (st * ASZ + r * LDT) * 4 + sg * 16,
                 A + (size_t)(m0 + r) * VISD + k0 + sg * 4);
        }
        #pragma unroll
        for (int j = 0; j < BN / 32; j++) {
            int i = tid + j * 256;
            int r = i >> 3, sg = i & 7;
            cp16(sWu + (st * WSZ + r * LDT) * 4 + sg * 16,
                 W + (size_t)r * VISD + k0 + sg * 4);
        }
    };

    const int lane = tid & 31, warp = tid >> 5;
    const int g = lane >> 2, t = lane & 3;
    const int wm = warp % WM, wn = warp / WM;
    const int mbase = wm * 32;
    const int nbase = wn * (BN / WN);

    const uint32_t rowA  = ((lane >> 3) & 1) * 8 + (lane & 7);
    const uint32_t abyte = (lane >> 4) * 16;
    const uint32_t rowB  = ((lane >> 4) << 3) + (lane & 7);
    const uint32_t bbyte = ((lane >> 3) & 1) * 16;

    float acc[2][TN][4] = {};

    load_tiles(0); cp_commit();
    load_tiles(1); cp_commit();
    load_tiles(2); cp_commit();

    for (int c = 0; c < NC; c++) {
        cp_wait<2>();
        __syncthreads();
        if (c + 3 < NC) load_tiles(c + 3);
        cp_commit();

        const uint32_t stA = sAu + (c % S) * ASZ * 4;
        const uint32_t stW = sWu + (c % S) * WSZ * 4;

        #pragma unroll
        for (int ks = 0; ks < 4; ks++) {
            uint32_t af[2][4], bf4[4];
            #pragma unroll
            for (int tm = 0; tm < 2; tm++)
                ldsm4(af[tm], stA + (mbase + tm * 16 + rowA) * (LDT * 4)
                              + ks * 32 + abyte);
            ldsm4(bf4, stW + (nbase + rowB) * (LDT * 4) + ks * 32 + bbyte);
            #pragma unroll
            for (int tm = 0; tm < 2; tm++) {
                mma_tf32(acc[tm][0], af[tm], bf4 + 0);
                mma_tf32(acc[tm][1], af[tm], bf4 + 2);
            }
        }
    }

    #pragma unroll
    for (int tm = 0; tm < 2; tm++) {
        #pragma unroll
        for (int tn = 0; tn < TN; tn++) {
            const int ncol = nbase + tn * 8 + 2 * t;
            const float b0 = sbias[ncol], b1 = sbias[ncol + 1];
            #pragma unroll
            for (int half = 0; half < 2; half++) {
                const int row = m0 + mbase + tm * 16 + g + half * 8;
                float vx = acc[tm][tn][half * 2 + 0] + b0;
                float vy = acc[tm][tn][half * 2 + 1] + b1;
                *(uint32_t*)(g_xh + (size_t)row * 384 + 320 + ncol) =
                    pack_bf16(vx, vy);
            }
        }
    }
}

// ---------------------------------------------------------------------------
// MLP bf16 GEMM: 128-thread CTA (4 warps), warp tile 32x128, ~240 regs/thread.
// BM=BN=128, BK=32, 3-stage cp.async, single barrier per iteration.
// ---------------------------------------------------------------------------
#define MLP_DECL                                                              \
    constexpr int BK = 32, S = 3, LDW = 20;                                   \
    constexpr int BM = 128, BN = 128, TN = 16;                                \
    constexpr int ASZ = BM * LDW;                                             \
    constexpr int WSZ = BN * LDW;                                             \
    (void)0

#define MLP_LOADER(Aptr, lda, Wptr, Kdim)                                     \
    auto load_tiles = [&](int c) {                                            \
        const int st = c % S;                                                 \
        const int k0 = c * BK;                                                \
        _Pragma("unroll")                                                     \
        for (int j = 0; j < 4; j++) {                                         \
            int i = tid + j * 128;                                            \
            int r = i >> 2, sg = i & 3;                                       \
            cp16(sAu + (st * ASZ + r * LDW + sg * 4) * 4,                     \
                 Aptr + (size_t)(m0 + r) * lda + k0 + sg * 8);                \
        }                                                                     \
        _Pragma("unroll")                                                     \
        for (int j = 0; j < 4; j++) {                                         \
            int i = tid + j * 128;                                            \
            int r = i >> 2, sg = i & 3;                                       \
            cp16(sWu + (st * WSZ + r * LDW + sg * 4) * 4,                     \
                 Wptr + (size_t)(n0 + r) * Kdim + k0 + sg * 8);               \
        }                                                                     \
    }

#define MLP_COMMON_IDX                                                        \
    const int lane = tid & 31, warp = tid >> 5;                               \
    const int g = lane >> 2, t = lane & 3;                                    \
    const int mbase = warp * 32;                                              \
    const uint32_t rowA  = ((lane >> 3) & 1) * 8 + (lane & 7);                \
    const uint32_t abyte = (lane >> 4) * 16;                                  \
    const uint32_t rowB  = ((lane >> 4) << 3) + (lane & 7);                   \
    const uint32_t bbyte = ((lane >> 3) & 1) * 16

#define MLP_MAINLOOP(NC)                                                      \
    load_tiles(0); cp_commit();                                               \
    load_tiles(1); cp_commit();                                               \
    for (int c = 0; c < (NC); c++) {                                          \
        cp_wait<1>();                                                         \
        __syncthreads();                                                      \
        if (c + 2 < (NC)) load_tiles(c + 2);                                  \
        cp_commit();                                                          \
        const uint32_t stA = sAu + (c % S) * ASZ * 4;                         \
        const uint32_t stW = sWu + (c % S) * WSZ * 4;                         \
        _Pragma("unroll")                                                     \
        for (int ks = 0; ks < 2; ks++) {                                      \
            uint32_t af[2][4], bf[8][4];                                      \
            _Pragma("unroll")                                                 \
            for (int tm = 0; tm < 2; tm++)                                    \
                ldsm4(af[tm], stA + (mbase + tm * 16 + rowA) * (LDW * 4)      \
                              + ks * 32 + abyte);                             \
            _Pragma("unroll")                                                 \
            for (int p = 0; p < 8; p++)                                       \
                ldsm4(bf[p], stW + (p * 16 + rowB) * (LDW * 4)                \
                              + ks * 32 + bbyte);                             \
            _Pragma("unroll")                                                 \
            for (int tm = 0; tm < 2; tm++)                                    \
                _Pragma("unroll")                                             \
                for (int p = 0; p < 8; p++) {                                 \
                    mma_bf16(acc[tm][2 * p],     af[tm], bf[p] + 0);          \
                    mma_bf16(acc[tm][2 * p + 1], af[tm], bf[p] + 2);          \
                }                                                             \
        }                                                                     \
    }

// ---------------------------------------------------------------------------
// mlp1: h1 = relu(x @ w1^T + b1) -> bf16
// ---------------------------------------------------------------------------
__global__ __launch_bounds__(128, 2) void gemm_mlp1(
    const __nv_bfloat16* __restrict__ A,
    const __nv_bfloat16* __restrict__ W,
    const float* __restrict__ bias,
    __nv_bfloat16* __restrict__ C)
{
    MLP_DECL;
    extern __shared__ uint32_t smw[];
    uint32_t* sA = smw;
    uint32_t* sW = smw + S * ASZ;
    __shared__ float sbias[BN];

    const int tid = threadIdx.x;
    const int m0  = blockIdx.y * BM;
    const int n0  = blockIdx.x * BN;

    sbias[tid] = bias[n0 + tid];

    const uint32_t sAu = smem_u32(sA);
    const uint32_t sWu = smem_u32(sW);
    MLP_LOADER(A, 384, W, 384);
    MLP_COMMON_IDX;

    float acc[2][TN][4] = {};
    MLP_MAINLOOP(384 / BK);

    #pragma unroll
    for (int tm = 0; tm < 2; tm++) {
        #pragma unroll
        for (int tn = 0; tn < TN; tn++) {
            const int ncol = tn * 8 + 2 * t;
            const float b0 = sbias[ncol], b1 = sbias[ncol + 1];
            const int gcol = n0 + ncol;
            #pragma unroll
            for (int half = 0; half < 2; half++) {
                const int row = m0 + mbase + tm * 16 + g + half * 8;
                float vx = fmaxf(acc[tm][tn][half * 2 + 0] + b0, 0.f);
                float vy = fmaxf(acc[tm][tn][half * 2 + 1] + b1, 0.f);
                *(uint32_t*)(C + (size_t)row * HID + gcol) = pack_bf16(vx, vy);
            }
        }
    }
}

// ---------------------------------------------------------------------------
// mlp2 + fused logits: h2 in regs only -> per-block logit partials
// ---------------------------------------------------------------------------
__global__ __launch_bounds__(128, 2) void gemm_mlp2_last(
    const __nv_bfloat16* __restrict__ A,
    const __nv_bfloat16* __restrict__ W,
    const float* __restrict__ bias,
    const float* __restrict__ w3)
{
    MLP_DECL;
    extern __shared__ uint32_t smw[];
    uint32_t* sA = smw;
    uint32_t* sW = smw + S * ASZ;
    __shared__ float sbias[BN];
    __shared__ float w3s[2][BN];

    const int tid = threadIdx.x;
    const int m0  = blockIdx.y * BM;
    const int n0  = blockIdx.x * BN;

    sbias[tid]  = bias[n0 + tid];
    w3s[0][tid] = w3[n0 + tid];
    w3s[1][tid] = w3[HID + n0 + tid];

    const uint32_t sAu = smem_u32(sA);
    const uint32_t sWu = smem_u32(sW);
    MLP_LOADER(A, HID, W, HID);
    MLP_COMMON_IDX;

    float acc[2][TN][4] = {};
    MLP_MAINLOOP(HID / BK);

    #pragma unroll
    for (int tm = 0; tm < 2; tm++) {
        #pragma unroll
        for (int half = 0; half < 2; half++) {
            const int row = m0 + mbase + tm * 16 + g + half * 8;
            float s0 = 0.f, s1 = 0.f;
            #pragma unroll
            for (int tn = 0; tn < TN; tn++) {
                const int ncol = tn * 8 + 2 * t;
                float v0 = fmaxf(acc[tm][tn][half * 2 + 0] + sbias[ncol],     0.f);
                float v1 = fmaxf(acc[tm][tn][half * 2 + 1] + sbias[ncol + 1], 0.f);
                s0 = fmaf(v0, w3s[0][ncol], fmaf(v1, w3s[0][ncol + 1], s0));
                s1 = fmaf(v0, w3s[1][ncol], fmaf(v1, w3s[1][ncol + 1], s1));
            }
            s0 += __shfl_xor_sync(0xffffffffu, s0, 1);
            s0 += __shfl_xor_sync(0xffffffffu, s0, 2);
            s1 += __shfl_xor_sync(0xffffffffu, s1, 1);
            s1 += __shfl_xor_sync(0xffffffffu, s1, 2);
            if (t == 0)
                g_part[row * 4 + blockIdx.x] = make_float2(s0, s1);
        }
    }
}

// ---------------------------------------------------------------------------
// Embeddings + FM (1st + 2nd order) -> g_xh[:, 0:320], g_fm
// ---------------------------------------------------------------------------
__global__ void embed_fm_kernel(
    const int* __restrict__ uid, const int* __restrict__ hour,
    const float* __restrict__ scale,
    const int* __restrict__ gender, const int* __restrict__ age,
    const int* __restrict__ attr,
    const float* __restrict__ user_emb, const float* __restrict__ hour_emb,
    const float* __restrict__ gender_emb, const float* __restrict__ age_emb,
    const float* __restrict__ attr_emb,
    const float* __restrict__ fm_w, const float* __restrict__ fm_b)
{
    int s = threadIdx.x >> 6;
    int k = threadIdx.x & 63;
    int b = blockIdx.x * 4 + s;

    int u  = uid[b];
    int h  = hour[b];
    int g  = gender[b];
    int a  = age[b];
    int at = attr[b];
    float sc = scale[b];

    float e0 = user_emb[(size_t)u * 64 + k];
    float e1 = hour_emb[h * 64 + k];
    float e2 = sc * tanhf(gender_emb[g * 64 + k]);
    float e3 = sc * tanhf(attr_emb[at * 64 + k]);
    float e4 = sc * tanhf(age_emb[a * 64 + k]);

    __nv_bfloat16* xb = g_xh + (size_t)b * 384;
    xb[      k] = __float2bfloat16_rn(e0);
    xb[ 64 + k] = __float2bfloat16_rn(e1);
    xb[128 + k] = __float2bfloat16_rn(e2);
    xb[192 + k] = __float2bfloat16_rn(e3);
    xb[256 + k] = __float2bfloat16_rn(e4);

    float su = e0 + e1 + e2 + e3 + e4;
    float sq = e0*e0 + e1*e1 + e2*e2 + e3*e3 + e4*e4;
    float so = su * su - sq;

    #pragma unroll
    for (int o = 16; o > 0; o >>= 1)
        so += __shfl_down_sync(0xffffffffu, so, o);

    __shared__ float red[4][2];
    if ((k & 31) == 0) red[s][k >> 5] = so;
    __syncthreads();

    if (k == 0) {
        float second = 0.5f * (red[s][0] + red[s][1]);
        long c0 = u;
        long c1 = NUSERS + h;
        long c2 = NUSERS + 24 + g;
        long c3 = NUSERS + 26 + a;
        long c4 = NUSERS + 34 + at;
        #pragma unroll
        for (int j = 0; j < 2; j++) {
            const float* w = fm_w + (size_t)j * VOCAB;
            g_fm[b * 2 + j] =
                w[c0] + w[c1] + w[c2] + w[c3] + w[c4] + fm_b[j] + second;
        }
    }
}

// ---------------------------------------------------------------------------
// Softmax over (fm + b3 + sum of 4 partials), fixed summation order.
// ---------------------------------------------------------------------------
__global__ void softmax_kernel(const float* __restrict__ b3,
                               float* __restrict__ out)
{
    int b = blockIdx.x * 256 + threadIdx.x;
    float s0 = 0.f, s1 = 0.f;
    #pragma unroll
    for (int p = 0; p < 4; p++) {
        float2 v = g_part[b * 4 + p];
        s0 += v.x; s1 += v.y;
    }
    float l0 = g_fm[b * 2 + 0] + b3[0] + s0;
    float l1 = g_fm[b * 2 + 1] + b3[1] + s1;
    float m  = fmaxf(l0, l1);
    float e0 = expf(l0 - m), e1 = expf(l1 - m);
    float inv = 1.0f / (e0 + e1);
    out[b * 2 + 0] = e0 * inv;
    out[b * 2 + 1] = e1 * inv;
}

// ---------------------------------------------------------------------------
extern "C" void kernel_launch(void* const* d_in, const int* in_sizes, int n_in,
                              void* d_out, int out_size)
{
    const int*   uid        = (const int*)  d_in[0];
    const int*   hour       = (const int*)  d_in[1];
    const float* visual     = (const float*)d_in[2];
    const float* scale      = (const float*)d_in[3];
    const int*   gender     = (const int*)  d_in[4];
    const int*   age        = (const int*)  d_in[5];
    const int*   attribute  = (const int*)  d_in[6];
    const float* user_emb   = (const float*)d_in[7];
    const float* hour_emb   = (const float*)d_in[8];
    const float* gender_emb = (const float*)d_in[9];
    const float* age_emb    = (const float*)d_in[10];
    const float* attr_emb   = (const float*)d_in[11];
    const float* visu_w     = (const float*)d_in[12];
    const float* visu_b     = (const float*)d_in[13];
    const float* fm_w       = (const float*)d_in[14];
    const float* fm_b       = (const float*)d_in[15];
    const float* w1         = (const float*)d_in[16];
    const float* b1         = (const float*)d_in[17];
    const float* w2         = (const float*)d_in[18];
    const float* b2         = (const float*)d_in[19];
    const float* w3         = (const float*)d_in[20];
    const float* b3         = (const float*)d_in[21];
    float* out = (float*)d_out;

    __nv_bfloat16 *xhp, *h1p, *w1p, *w2p;
    cudaGetSymbolAddress((void**)&xhp, g_xh);
    cudaGetSymbolAddress((void**)&h1p, g_h1h);
    cudaGetSymbolAddress((void**)&w1p, g_w1h);
    cudaGetSymbolAddress((void**)&w2p, g_w2h);

    const int SM_VIS = 4 * (64 + 64) * 36 * 4;           // 73,728 B
    const int SM_MLP = 3 * (128 + 128) * 20 * 4;         // 61,440 B
    cudaFuncSetAttribute(gemm_tf32_vis,  cudaFuncAttributeMaxDynamicSharedMemorySize, SM_VIS);
    cudaFuncSetAttribute(gemm_mlp1,      cudaFuncAttributeMaxDynamicSharedMemorySize, SM_MLP);
    cudaFuncSetAttribute(gemm_mlp2_last, cudaFuncAttributeMaxDynamicSharedMemorySize, SM_MLP);

    // fork two side branches off the capture stream
    cudaStream_t s1, s2;
    cudaStreamCreateWithFlags(&s1, cudaStreamNonBlocking);
    cudaStreamCreateWithFlags(&s2, cudaStreamNonBlocking);
    cudaEvent_t ev0, ev1, ev2;
    cudaEventCreateWithFlags(&ev0, cudaEventDisableTiming);
    cudaEventCreateWithFlags(&ev1, cudaEventDisableTiming);
    cudaEventCreateWithFlags(&ev2, cudaEventDisableTiming);

    cudaEventRecord(ev0, 0);
    cudaStreamWaitEvent(s1, ev0, 0);
    cudaStreamWaitEvent(s2, ev0, 0);

    // branch 1 (s1): vis = visual @ visu_w^T + visu_b -> bf16 x[:,320:384]
    gemm_tf32_vis<<<BATCH / 64, 256, SM_VIS, s1>>>(visual, visu_w, visu_b, xhp);

    // branch 2 (s2): weight conversion
    conv_w_kernel<<<448, 256, 0, s2>>>(w1, w2);

    // main stream: embeddings + FM
    embed_fm_kernel<<<BATCH / 4, 256>>>(uid, hour, scale, gender, age, attribute,
                                        user_emb, hour_emb, gender_emb, age_emb,
                                        attr_emb, fm_w, fm_b);

    cudaEventRecord(ev1, s1);
    cudaEventRecord(ev2, s2);
    cudaStreamWaitEvent(0, ev1, 0);
    cudaStreamWaitEvent(0, ev2, 0);

    // h1 = relu(x @ w1^T + b1)  — 128-thread CTAs, high-ILP config
    gemm_mlp1<<<dim3(HID / 128, BATCH / 128), 128, SM_MLP>>>(xhp, w1p, b1, h1p);

    // h2 (registers only) -> logit partials
    gemm_mlp2_last<<<dim3(HID / 128, BATCH / 128), 128, SM_MLP>>>(h1p, w2p, b2, w3);

    // softmax(fm + b3 + sum partials)
    softmax_kernel<<<BATCH / 256, 256>>>(b3, out);

    cudaEventDestroy(ev0);
    cudaEventDestroy(ev1);
    cudaEventDestroy(ev2);
    cudaStreamDestroy(s1);
    cudaStreamDestroy(s2);
}